// round 13
// baseline (speedup 1.0000x reference)
#include <cuda_runtime.h>
#include <cuda_bf16.h>
#include <math.h>
#include <stdint.h>

// Problem constants
#define B_SZ   2
#define LSEQ   2048
#define DMODEL 1024
#define DINNER 2048
#define DSTATE 16
#define DCONV  4
#define DTRANK 64
#define BL     (B_SZ * LSEQ)          // 4096 rows
#define XDW    128                    // padded x_dbl width (dt 0..63, B 64..79, C 80..95)
#define NCHK   16
#define TCH    (LSEQ / NCHK)          // 128
#define KSPLIT 4

// ---------------- scratch ----------------
__device__ float g_xz[(size_t)BL * (2 * DINNER)];
__device__ float g_u[(size_t)BL * DINNER];
__device__ float g_xdbl[(size_t)BL * XDW];
__device__ float g_delta[(size_t)BL * DINNER];
__device__ float g_part[(size_t)KSPLIT * BL * XDW];    // split-K partials for GEMM3
__device__ float g_hloc[(size_t)NCHK * DSTATE * BL];   // [chunk][n][ch]
__device__ float g_h0[(size_t)NCHK * DSTATE * BL];
__device__ float g_sumdt[(size_t)NCHK * BL];

__device__ __nv_bfloat16 g_xh[(size_t)BL * DMODEL],   g_xl[(size_t)BL * DMODEL];
__device__ __nv_bfloat16 g_wih[(size_t)DMODEL * 2 * DINNER], g_wil[(size_t)DMODEL * 2 * DINNER];
__device__ __nv_bfloat16 g_woh[(size_t)DINNER * DMODEL],     g_wol[(size_t)DINNER * DMODEL];
__device__ __nv_bfloat16 g_wdh[(size_t)DTRANK * DINNER],     g_wdl[(size_t)DTRANK * DINNER];
__device__ __nv_bfloat16 g_wxh[(size_t)DINNER * XDW],        g_wxl[(size_t)DINNER * XDW];
__device__ __nv_bfloat16 g_uh[(size_t)BL * DINNER],  g_ul[(size_t)BL * DINNER];
__device__ __nv_bfloat16 g_dth[(size_t)BL * XDW],    g_dtl[(size_t)BL * XDW];
__device__ __nv_bfloat16 g_yh[(size_t)BL * DINNER],  g_yl[(size_t)BL * DINNER];

// ---------------- helpers ----------------
__device__ __forceinline__ float softplus_f(float x) {
    return (x > 20.f) ? x : log1pf(expf(x));
}
__device__ __forceinline__ float silu_f(float x) {
    return x * (1.f / (1.f + __expf(-x)));
}
__device__ __forceinline__ void split_hl(float v, __nv_bfloat16& h, __nv_bfloat16& l) {
    h = __float2bfloat16_rn(v);
    l = __float2bfloat16_rn(v - __bfloat162float(h));
}

// fp32 -> (hi, lo) bf16, 4 elems/thread
__global__ void cvt_hilo_k(const float* __restrict__ s, __nv_bfloat16* __restrict__ h,
                           __nv_bfloat16* __restrict__ l, int n4)
{
    int i = blockIdx.x * blockDim.x + threadIdx.x;
    if (i >= n4) return;
    float4 v = ((const float4*)s)[i];
    __nv_bfloat16 h0, h1, h2, h3, l0, l1, l2, l3;
    split_hl(v.x, h0, l0); split_hl(v.y, h1, l1);
    split_hl(v.z, h2, l2); split_hl(v.w, h3, l3);
    ((__nv_bfloat162*)h)[i * 2]     = __nv_bfloat162(h0, h1);
    ((__nv_bfloat162*)h)[i * 2 + 1] = __nv_bfloat162(h2, h3);
    ((__nv_bfloat162*)l)[i * 2]     = __nv_bfloat162(l0, l1);
    ((__nv_bfloat162*)l)[i * 2 + 1] = __nv_bfloat162(l2, l3);
}

// W_x [2048,96] -> padded hi/lo [2048,128] (cols >=96 zero)
__global__ void cvt_pad_wx_k(const float* __restrict__ s, __nv_bfloat16* __restrict__ h,
                             __nv_bfloat16* __restrict__ l)
{
    int i = blockIdx.x * blockDim.x + threadIdx.x;   // over 2048*128
    int col = i & (XDW - 1), k = i >> 7;
    float v = (col < 96) ? s[k * 96 + col] : 0.f;
    __nv_bfloat16 hh, ll; split_hl(v, hh, ll);
    h[i] = hh; l[i] = ll;
}

// split-K reduction for GEMM3: xdbl = sum parts, also dt hi/lo
__global__ void reduce_xdbl_k(float* __restrict__ xdbl,
                              __nv_bfloat16* __restrict__ dth, __nv_bfloat16* __restrict__ dtl)
{
    const int i = blockIdx.x * blockDim.x + threadIdx.x;   // over BL*XDW
    float v = g_part[i];
#pragma unroll
    for (int p = 1; p < KSPLIT; ++p) v += g_part[(size_t)p * BL * XDW + i];
    xdbl[i] = v;
    __nv_bfloat16 hh, ll; split_hl(v, hh, ll);
    dth[i] = hh; dtl[i] = ll;
}

// ---------------- tensor-core GEMM: 3x-split bf16 mma.sync ----------------
#define CP16(dst, src) \
    asm volatile("cp.async.cg.shared.global [%0], [%1], 16;" :: "r"(dst), "l"(src))
#define CP_COMMIT() asm volatile("cp.async.commit_group;" ::: "memory")
#define LDSM4(r, addr) \
    asm volatile("ldmatrix.sync.aligned.m8n8.x4.shared.b16 {%0,%1,%2,%3}, [%4];" \
        : "=r"((r)[0]), "=r"((r)[1]), "=r"((r)[2]), "=r"((r)[3]) : "r"(addr))
#define LDSM4T(r, addr) \
    asm volatile("ldmatrix.sync.aligned.m8n8.x4.trans.shared.b16 {%0,%1,%2,%3}, [%4];" \
        : "=r"((r)[0]), "=r"((r)[1]), "=r"((r)[2]), "=r"((r)[3]) : "r"(addr))
#define MMA16816(d, a, b0r, b1r) \
    asm volatile("mma.sync.aligned.m16n8k16.row.col.f32.bf16.bf16.f32 " \
        "{%0,%1,%2,%3}, {%4,%5,%6,%7}, {%8,%9}, {%0,%1,%2,%3};" \
        : "+f"((d)[0]), "+f"((d)[1]), "+f"((d)[2]), "+f"((d)[3]) \
        : "r"((a)[0]), "r"((a)[1]), "r"((a)[2]), "r"((a)[3]), "r"(b0r), "r"(b1r))

#define A_STRIDE 40      // bf16 units; 80 B rows -> conflict-free LDSM
#define B_STRIDE 136     // 272 B rows -> conflict-free LDSM.trans
#define B_MAT_SZ (32 * B_STRIDE)

// C[M,N] fp32 = (Ah+Al)[M,K](astr) @ (Bh+Bl)[K,N], drop Al*Bl.
// 2-stage cp.async pipeline. R8-exact hot kernel — DO NOT add runtime params
// (register-critical under launch_bounds(256,2); R10 spill regression).
// mode 0: plain; mode 1: softplus(acc+bias); mode 2: plain + hi/lo into Ch/Cl.
template<int BM>
__global__ __launch_bounds__(256, 2)
void gemm_bf16x3_k(const __nv_bfloat16* __restrict__ Ah, const __nv_bfloat16* __restrict__ Al,
                   const __nv_bfloat16* __restrict__ Bh, const __nv_bfloat16* __restrict__ Bl,
                   float* __restrict__ C, int M, int N, int K, int astr,
                   const float* __restrict__ bias, int mode,
                   __nv_bfloat16* __restrict__ Ch, __nv_bfloat16* __restrict__ Cl)
{
    constexpr int MT      = BM / 32;                 // 4 (BM=128) or 2 (BM=64)
    constexpr int WM      = BM / 2;                  // warp tile M
    constexpr int A_MAT   = BM * A_STRIDE;
    constexpr int STAGE   = 2 * A_MAT + 2 * B_MAT_SZ;

    extern __shared__ __align__(16) __nv_bfloat16 sm[];
    const uint32_t smbase = (uint32_t)__cvta_generic_to_shared(sm);

    const int tid  = threadIdx.x;
    const int lane = tid & 31;
    const int w    = tid >> 5;
    const int wm   = w >> 2;          // 0..1
    const int wn   = w & 3;           // 0..3
    const int bm   = blockIdx.y * BM;
    const int bn   = blockIdx.x * 128;

    const __nv_bfloat16* Asrc[2] = {Ah, Al};
    const __nv_bfloat16* Bsrc[2] = {Bh, Bl};

    auto fill = [&](int stg, int k0) {
        const uint32_t stgA = smbase + (uint32_t)(stg * STAGE) * 2;
        const uint32_t stgB = stgA + (uint32_t)(2 * A_MAT) * 2;
#pragma unroll
        for (int mat = 0; mat < 2; ++mat) {
#pragma unroll
            for (int i = 0; i < BM * 4 / 256; ++i) {
                int c = tid + i * 256;
                int r = c >> 2, kc = (c & 3) << 3;
                uint32_t dst = stgA + (uint32_t)(mat * A_MAT + r * A_STRIDE + kc) * 2;
                CP16(dst, Asrc[mat] + (size_t)(bm + r) * astr + k0 + kc);
            }
        }
#pragma unroll
        for (int mat = 0; mat < 2; ++mat) {
#pragma unroll
            for (int i = 0; i < 2; ++i) {
                int c = tid + i * 256;
                int r = c >> 4, nc = (c & 15) << 3;
                uint32_t dst = stgB + (uint32_t)(mat * B_MAT_SZ + r * B_STRIDE + nc) * 2;
                CP16(dst, Bsrc[mat] + (size_t)(k0 + r) * N + bn + nc);
            }
        }
    };

    float acc[MT][4][4];
#pragma unroll
    for (int i = 0; i < MT; ++i)
#pragma unroll
        for (int j = 0; j < 4; ++j)
#pragma unroll
            for (int q = 0; q < 4; ++q) acc[i][j][q] = 0.f;

    const uint32_t aByte = (uint32_t)((wm * WM + (lane & 15)) * A_STRIDE + ((lane >> 4) << 3)) * 2;
    const uint32_t bByte = (uint32_t)((lane & 15) * B_STRIDE + wn * 32 + ((lane >> 4) << 3)) * 2;

    const int KT = K >> 5;
    fill(0, 0);
    CP_COMMIT();

    for (int it = 0; it < KT; ++it) {
        const int cur = it & 1;
        if (it + 1 < KT) { fill(cur ^ 1, (it + 1) << 5); CP_COMMIT(); }
        if (it + 1 < KT) asm volatile("cp.async.wait_group 1;" ::: "memory");
        else             asm volatile("cp.async.wait_group 0;" ::: "memory");
        __syncthreads();

        const uint32_t stgA = smbase + (uint32_t)(cur * STAGE) * 2;
        const uint32_t stgB = stgA + (uint32_t)(2 * A_MAT) * 2;

#pragma unroll
        for (int ks = 0; ks < 32; ks += 16) {
            uint32_t bhf[2][4], blf[2][4];
#pragma unroll
            for (int p = 0; p < 2; ++p) {
                uint32_t off = bByte + (uint32_t)(ks * B_STRIDE + p * 16) * 2;
                LDSM4T(bhf[p], stgB + off);
                LDSM4T(blf[p], stgB + (uint32_t)(B_MAT_SZ * 2) + off);
            }
#pragma unroll
            for (int mt = 0; mt < MT; ++mt) {
                uint32_t ahf[4], alf[4];
                uint32_t off = aByte + (uint32_t)(mt * 16 * A_STRIDE + ks) * 2;
                LDSM4(ahf, stgA + off);
                LDSM4(alf, stgA + (uint32_t)(A_MAT * 2) + off);
#pragma unroll
                for (int nt = 0; nt < 4; ++nt) {
                    const int p = nt >> 1, q = (nt & 1) << 1;
                    MMA16816(acc[mt][nt], ahf, bhf[p][q], bhf[p][q + 1]); // hi*hi
                    MMA16816(acc[mt][nt], ahf, blf[p][q], blf[p][q + 1]); // hi*lo
                    MMA16816(acc[mt][nt], alf, bhf[p][q], bhf[p][q + 1]); // lo*hi
                }
            }
        }
        __syncthreads();
    }

#pragma unroll
    for (int mt = 0; mt < MT; ++mt) {
        const int r0 = bm + wm * WM + mt * 16 + (lane >> 2);
#pragma unroll
        for (int nt = 0; nt < 4; ++nt) {
            const int c0 = bn + wn * 32 + nt * 8 + ((lane & 3) << 1);
            float v0 = acc[mt][nt][0], v1 = acc[mt][nt][1];
            float v2 = acc[mt][nt][2], v3 = acc[mt][nt][3];
            if (mode == 1) {
                const float b0 = bias[c0], b1 = bias[c0 + 1];
                v0 = softplus_f(v0 + b0); v1 = softplus_f(v1 + b1);
                v2 = softplus_f(v2 + b0); v3 = softplus_f(v3 + b1);
            }
            *(float2*)(C + (size_t)r0 * N + c0)       = make_float2(v0, v1);
            *(float2*)(C + (size_t)(r0 + 8) * N + c0) = make_float2(v2, v3);
            if (mode == 2) {
                __nv_bfloat16 h0, l0, h1, l1, h2, l2, h3, l3;
                split_hl(v0, h0, l0); split_hl(v1, h1, l1);
                split_hl(v2, h2, l2); split_hl(v3, h3, l3);
                *(__nv_bfloat162*)(Ch + (size_t)r0 * N + c0)       = __nv_bfloat162(h0, h1);
                *(__nv_bfloat162*)(Cl + (size_t)r0 * N + c0)       = __nv_bfloat162(l0, l1);
                *(__nv_bfloat162*)(Ch + (size_t)(r0 + 8) * N + c0) = __nv_bfloat162(h2, h3);
                *(__nv_bfloat162*)(Cl + (size_t)(r0 + 8) * N + c0) = __nv_bfloat162(l2, l3);
            }
        }
    }
}

// ---------------- dedicated split-K GEMM3 kernel (all shapes compile-time) ----------------
// part[s][BL][XDW] = u[:, s*512:(s+1)*512] @ Wx[s*512:(s+1)*512, :]
__global__ __launch_bounds__(256, 2)
void gemm3_splitk_k(const __nv_bfloat16* __restrict__ Ah, const __nv_bfloat16* __restrict__ Al,
                    const __nv_bfloat16* __restrict__ Bh, const __nv_bfloat16* __restrict__ Bl,
                    float* __restrict__ Cbase)
{
    constexpr int BM   = 64;
    constexpr int MT   = 2;
    constexpr int WM   = 32;
    constexpr int A_MAT = BM * A_STRIDE;
    constexpr int STAGE = 2 * A_MAT + 2 * B_MAT_SZ;
    constexpr int N    = XDW;
    constexpr int KSEG = DINNER / KSPLIT;   // 512
    constexpr int KT   = KSEG / 32;         // 16

    extern __shared__ __align__(16) __nv_bfloat16 sm[];
    const uint32_t smbase = (uint32_t)__cvta_generic_to_shared(sm);

    const int tid  = threadIdx.x;
    const int lane = tid & 31;
    const int w    = tid >> 5;
    const int wm   = w >> 2;
    const int wn   = w & 3;
    const int bm   = blockIdx.y * BM;
    const int kbase = blockIdx.x * KSEG;
    float* __restrict__ C = Cbase + (size_t)blockIdx.x * BL * XDW;

    const __nv_bfloat16* Asrc[2] = {Ah, Al};
    const __nv_bfloat16* Bsrc[2] = {Bh, Bl};

    auto fill = [&](int stg, int k0) {
        const uint32_t stgA = smbase + (uint32_t)(stg * STAGE) * 2;
        const uint32_t stgB = stgA + (uint32_t)(2 * A_MAT) * 2;
#pragma unroll
        for (int mat = 0; mat < 2; ++mat) {
            int c = tid;                      // BM*4/256 == 1 pass
            int r = c >> 2, kc = (c & 3) << 3;
            uint32_t dst = stgA + (uint32_t)(mat * A_MAT + r * A_STRIDE + kc) * 2;
            CP16(dst, Asrc[mat] + (size_t)(bm + r) * DINNER + k0 + kc);
        }
#pragma unroll
        for (int mat = 0; mat < 2; ++mat) {
#pragma unroll
            for (int i = 0; i < 2; ++i) {
                int c = tid + i * 256;
                int r = c >> 4, nc = (c & 15) << 3;
                uint32_t dst = stgB + (uint32_t)(mat * B_MAT_SZ + r * B_STRIDE + nc) * 2;
                CP16(dst, Bsrc[mat] + (size_t)(k0 + r) * N + nc);
            }
        }
    };

    float acc[MT][4][4];
#pragma unroll
    for (int i = 0; i < MT; ++i)
#pragma unroll
        for (int j = 0; j < 4; ++j)
#pragma unroll
            for (int q = 0; q < 4; ++q) acc[i][j][q] = 0.f;

    const uint32_t aByte = (uint32_t)((wm * WM + (lane & 15)) * A_STRIDE + ((lane >> 4) << 3)) * 2;
    const uint32_t bByte = (uint32_t)((lane & 15) * B_STRIDE + wn * 32 + ((lane >> 4) << 3)) * 2;

    fill(0, kbase);
    CP_COMMIT();

    for (int it = 0; it < KT; ++it) {
        const int cur = it & 1;
        if (it + 1 < KT) { fill(cur ^ 1, kbase + ((it + 1) << 5)); CP_COMMIT(); }
        if (it + 1 < KT) asm volatile("cp.async.wait_group 1;" ::: "memory");
        else             asm volatile("cp.async.wait_group 0;" ::: "memory");
        __syncthreads();

        const uint32_t stgA = smbase + (uint32_t)(cur * STAGE) * 2;
        const uint32_t stgB = stgA + (uint32_t)(2 * A_MAT) * 2;

#pragma unroll
        for (int ks = 0; ks < 32; ks += 16) {
            uint32_t bhf[2][4], blf[2][4];
#pragma unroll
            for (int p = 0; p < 2; ++p) {
                uint32_t off = bByte + (uint32_t)(ks * B_STRIDE + p * 16) * 2;
                LDSM4T(bhf[p], stgB + off);
                LDSM4T(blf[p], stgB + (uint32_t)(B_MAT_SZ * 2) + off);
            }
#pragma unroll
            for (int mt = 0; mt < MT; ++mt) {
                uint32_t ahf[4], alf[4];
                uint32_t off = aByte + (uint32_t)(mt * 16 * A_STRIDE + ks) * 2;
                LDSM4(ahf, stgA + off);
                LDSM4(alf, stgA + (uint32_t)(A_MAT * 2) + off);
#pragma unroll
                for (int nt = 0; nt < 4; ++nt) {
                    const int p = nt >> 1, q = (nt & 1) << 1;
                    MMA16816(acc[mt][nt], ahf, bhf[p][q], bhf[p][q + 1]);
                    MMA16816(acc[mt][nt], ahf, blf[p][q], blf[p][q + 1]);
                    MMA16816(acc[mt][nt], alf, bhf[p][q], bhf[p][q + 1]);
                }
            }
        }
        __syncthreads();
    }

#pragma unroll
    for (int mt = 0; mt < MT; ++mt) {
        const int r0 = bm + wm * WM + mt * 16 + (lane >> 2);
#pragma unroll
        for (int nt = 0; nt < 4; ++nt) {
            const int c0 = wn * 32 + nt * 8 + ((lane & 3) << 1);
            *(float2*)(C + (size_t)r0 * N + c0) =
                make_float2(acc[mt][nt][0], acc[mt][nt][1]);
            *(float2*)(C + (size_t)(r0 + 8) * N + c0) =
                make_float2(acc[mt][nt][2], acc[mt][nt][3]);
        }
    }
}

// ---------------- causal depthwise conv (width 4) + SiLU, x4 vectorized ----------------
// each thread: 4 consecutive channels d4..d4+3 of one (b,l) row
__global__ void conv_silu_kernel(const float* __restrict__ xz, const float* __restrict__ cw,
                                 const float* __restrict__ cb, float* __restrict__ u,
                                 __nv_bfloat16* __restrict__ uh, __nv_bfloat16* __restrict__ ul)
{
    const int i4 = blockIdx.x * blockDim.x + threadIdx.x;   // over BL*DINNER/4
    const int d4 = (i4 << 2) & (DINNER - 1);
    const int bl = i4 >> 9;                                 // DINNER/4 = 512
    const int l  = bl & (LSEQ - 1);

    float4 s = *(const float4*)(cb + d4);
    const float4 w0 = *(const float4*)(cw + (d4 + 0) * 4);  // taps of channel d4
    const float4 w1 = *(const float4*)(cw + (d4 + 1) * 4);
    const float4 w2 = *(const float4*)(cw + (d4 + 2) * 4);
    const float4 w3 = *(const float4*)(cw + (d4 + 3) * 4);

    const float* base = xz + (size_t)(bl - l) * (2 * DINNER) + d4;
#pragma unroll
    for (int k = 0; k < 4; ++k) {
        const int ls = l - 3 + k;
        if (ls >= 0) {
            const float4 xv = *(const float4*)(base + (size_t)ls * (2 * DINNER));
            s.x += xv.x * (&w0.x)[k];
            s.y += xv.y * (&w1.x)[k];
            s.z += xv.z * (&w2.x)[k];
            s.w += xv.w * (&w3.x)[k];
        }
    }
    const float u0 = silu_f(s.x), u1 = silu_f(s.y), u2 = silu_f(s.z), u3 = silu_f(s.w);
    const size_t idx = (size_t)bl * DINNER + d4;
    *(float4*)(u + idx) = make_float4(u0, u1, u2, u3);

    __nv_bfloat16 h0, l0, h1, l1, h2, l2, h3, l3;
    split_hl(u0, h0, l0); split_hl(u1, h1, l1);
    split_hl(u2, h2, l2); split_hl(u3, h3, l3);
    ((__nv_bfloat162*)(uh + idx))[0] = __nv_bfloat162(h0, h1);
    ((__nv_bfloat162*)(uh + idx))[1] = __nv_bfloat162(h2, h3);
    ((__nv_bfloat162*)(ul + idx))[0] = __nv_bfloat162(l0, l1);
    ((__nv_bfloat162*)(ul + idx))[1] = __nv_bfloat162(l2, l3);
}

// ---------------- chunked selective scan (R8-exact) ----------------
__global__ __launch_bounds__(128)
void scanA_k(const float* __restrict__ delta, const float* __restrict__ xdbl,
             const float* __restrict__ u, const float* __restrict__ A_log)
{
    __shared__ float sBC[4][32];
    const int tid = threadIdx.x;
    const int ch  = blockIdx.x * 128 + tid;
    const int b   = ch >> 11;
    const int d   = ch & (DINNER - 1);
    const int chunk = blockIdx.y;

    float Ar[16];
#pragma unroll
    for (int n = 0; n < 16; ++n) Ar[n] = -expf(A_log[d * DSTATE + n]);
    const float A0 = Ar[0];
    bool structured = true;
#pragma unroll
    for (int n = 1; n < 16; ++n)
        if (fabsf(Ar[n] - A0 * (float)(n + 1)) > 1e-4f * fabsf(Ar[n])) structured = false;

    float h[16];
#pragma unroll
    for (int n = 0; n < 16; ++n) h[n] = 0.f;
    float sumdt = 0.f;

    const size_t rowbase = (size_t)b * LSEQ + chunk * TCH;
    const int sj = tid >> 5, sc = tid & 31;

    for (int tt = 0; tt < TCH; tt += 4) {
        sBC[sj][sc] = xdbl[(rowbase + tt + sj) * XDW + DTRANK + sc];
        float cd[4], cu[4];
#pragma unroll
        for (int j = 0; j < 4; ++j) {
            const size_t ix = (rowbase + tt + j) * DINNER + d;
            cd[j] = delta[ix]; cu[j] = u[ix];
        }
        __syncthreads();
#pragma unroll
        for (int j = 0; j < 4; ++j) {
            const float dt = cd[j], du = dt * cu[j];
            sumdt += dt;
            if (structured) {
                const float p = __expf(dt * A0);
                float wv[16];
                wv[0] = p;
#pragma unroll
                for (int n = 1; n < 16; ++n) wv[n] = wv[(n - 1) >> 1] * wv[n >> 1];
#pragma unroll
                for (int n = 0; n < 16; ++n) h[n] = wv[n] * h[n] + sBC[j][n] * du;
            } else {
#pragma unroll
                for (int n = 0; n < 16; ++n)
                    h[n] = __expf(dt * Ar[n]) * h[n] + sBC[j][n] * du;
            }
        }
        __syncthreads();
    }
    g_sumdt[(size_t)chunk * BL + ch] = sumdt;
#pragma unroll
    for (int n = 0; n < 16; ++n)
        g_hloc[((size_t)chunk * DSTATE + n) * BL + ch] = h[n];
}

__global__ __launch_bounds__(128)
void scanB_k(const float* __restrict__ A_log)
{
    const int ch = blockIdx.x * 128 + threadIdx.x;
    const int d  = ch & (DINNER - 1);
    float Ar[16];
#pragma unroll
    for (int n = 0; n < 16; ++n) Ar[n] = -expf(A_log[d * DSTATE + n]);
    float h0[16];
#pragma unroll
    for (int n = 0; n < 16; ++n) h0[n] = 0.f;
    for (int c = 0; c < NCHK; ++c) {
#pragma unroll
        for (int n = 0; n < 16; ++n)
            g_h0[((size_t)c * DSTATE + n) * BL + ch] = h0[n];
        const float sd = g_sumdt[(size_t)c * BL + ch];
#pragma unroll
        for (int n = 0; n < 16; ++n)
            h0[n] = __expf(Ar[n] * sd) * h0[n] + g_hloc[((size_t)c * DSTATE + n) * BL + ch];
    }
}

__global__ __launch_bounds__(128)
void scanC_k(const float* __restrict__ delta, const float* __restrict__ xdbl,
             const float* __restrict__ u, const float* __restrict__ A_log,
             const float* __restrict__ Dv, const float* __restrict__ xz,
             __nv_bfloat16* __restrict__ yh, __nv_bfloat16* __restrict__ yl)
{
    __shared__ float sBC[4][32];
    const int tid = threadIdx.x;
    const int ch  = blockIdx.x * 128 + tid;
    const int b   = ch >> 11;
    const int d   = ch & (DINNER - 1);
    const int chunk = blockIdx.y;

    float Ar[16];
#pragma unroll
    for (int n = 0; n < 16; ++n) Ar[n] = -expf(A_log[d * DSTATE + n]);
    const float A0 = Ar[0];
    bool structured = true;
#pragma unroll
    for (int n = 1; n < 16; ++n)
        if (fabsf(Ar[n] - A0 * (float)(n + 1)) > 1e-4f * fabsf(Ar[n])) structured = false;

    const float Dd = Dv[d];
    float h[16];
#pragma unroll
    for (int n = 0; n < 16; ++n)
        h[n] = g_h0[((size_t)chunk * DSTATE + n) * BL + ch];

    const size_t rowbase = (size_t)b * LSEQ + chunk * TCH;
    const int sj = tid >> 5, sc = tid & 31;

    for (int tt = 0; tt < TCH; tt += 4) {
        sBC[sj][sc] = xdbl[(rowbase + tt + sj) * XDW + DTRANK + sc];
        float cd[4], cu[4], cr[4];
#pragma unroll
        for (int j = 0; j < 4; ++j) {
            const size_t ix = (rowbase + tt + j) * DINNER + d;
            cd[j] = delta[ix]; cu[j] = u[ix];
            cr[j] = xz[(rowbase + tt + j) * (2 * DINNER) + DINNER + d];
        }
        __syncthreads();
#pragma unroll
        for (int j = 0; j < 4; ++j) {
            const float dt = cd[j], ut = cu[j], du = dt * ut;
            float yv0 = 0.f, yv1 = 0.f, yv2 = 0.f, yv3 = 0.f;
            if (structured) {
                const float p = __expf(dt * A0);
                float wv[16];
                wv[0] = p;
#pragma unroll
                for (int n = 1; n < 16; ++n) wv[n] = wv[(n - 1) >> 1] * wv[n >> 1];
#pragma unroll
                for (int n = 0; n < 16; n += 4) {
                    h[n]     = wv[n]     * h[n]     + sBC[j][n]     * du;
                    h[n + 1] = wv[n + 1] * h[n + 1] + sBC[j][n + 1] * du;
                    h[n + 2] = wv[n + 2] * h[n + 2] + sBC[j][n + 2] * du;
                    h[n + 3] = wv[n + 3] * h[n + 3] + sBC[j][n + 3] * du;
                    yv0 += h[n]     * sBC[j][16 + n];
                    yv1 += h[n + 1] * sBC[j][16 + n + 1];
                    yv2 += h[n + 2] * sBC[j][16 + n + 2];
                    yv3 += h[n + 3] * sBC[j][16 + n + 3];
                }
            } else {
#pragma unroll
                for (int n = 0; n < 16; n += 4) {
                    const float w0 = __expf(dt * Ar[n]);
                    const float w1 = __expf(dt * Ar[n + 1]);
                    const float w2 = __expf(dt * Ar[n + 2]);
                    const float w3 = __expf(dt * Ar[n + 3]);
                    h[n]     = w0 * h[n]     + sBC[j][n]     * du;
                    h[n + 1] = w1 * h[n + 1] + sBC[j][n + 1] * du;
                    h[n + 2] = w2 * h[n + 2] + sBC[j][n + 2] * du;
                    h[n + 3] = w3 * h[n + 3] + sBC[j][n + 3] * du;
                    yv0 += h[n]     * sBC[j][16 + n];
                    yv1 += h[n + 1] * sBC[j][16 + n + 1];
                    yv2 += h[n + 2] * sBC[j][16 + n + 2];
                    yv3 += h[n + 3] * sBC[j][16 + n + 3];
                }
            }
            const float yv = (yv0 + yv1) + (yv2 + yv3);
            const float vout = (yv + ut * Dd) * silu_f(cr[j]);
            __nv_bfloat16 hh, ll; split_hl(vout, hh, ll);
            const size_t ix = (rowbase + tt + j) * DINNER + d;
            yh[ix] = hh; yl[ix] = ll;
        }
        __syncthreads();
    }
}

// ---------------- launch ----------------
extern "C" void kernel_launch(void* const* d_in, const int* in_sizes, int n_in,
                              void* d_out, int out_size)
{
    const float* x     = (const float*)d_in[0];
    const float* W_in  = (const float*)d_in[1];
    const float* convw = (const float*)d_in[2];
    const float* convb = (const float*)d_in[3];
    const float* W_x   = (const float*)d_in[4];
    const float* W_dt  = (const float*)d_in[5];
    const float* b_dt  = (const float*)d_in[6];
    const float* A_log = (const float*)d_in[7];
    const float* Dv    = (const float*)d_in[8];
    const float* W_out = (const float*)d_in[9];
    float* out = (float*)d_out;

    float *xz, *u, *xdbl, *delta, *part;
    __nv_bfloat16 *xh, *xl, *wih, *wil, *woh, *wol, *wdh, *wdl, *wxh, *wxl;
    __nv_bfloat16 *uh, *ul, *dth, *dtl, *yh, *yl;
    cudaGetSymbolAddress((void**)&xz,    g_xz);
    cudaGetSymbolAddress((void**)&u,     g_u);
    cudaGetSymbolAddress((void**)&xdbl,  g_xdbl);
    cudaGetSymbolAddress((void**)&delta, g_delta);
    cudaGetSymbolAddress((void**)&part,  g_part);
    cudaGetSymbolAddress((void**)&xh,  g_xh);  cudaGetSymbolAddress((void**)&xl,  g_xl);
    cudaGetSymbolAddress((void**)&wih, g_wih); cudaGetSymbolAddress((void**)&wil, g_wil);
    cudaGetSymbolAddress((void**)&woh, g_woh); cudaGetSymbolAddress((void**)&wol, g_wol);
    cudaGetSymbolAddress((void**)&wdh, g_wdh); cudaGetSymbolAddress((void**)&wdl, g_wdl);
    cudaGetSymbolAddress((void**)&wxh, g_wxh); cudaGetSymbolAddress((void**)&wxl, g_wxl);
    cudaGetSymbolAddress((void**)&uh,  g_uh);  cudaGetSymbolAddress((void**)&ul,  g_ul);
    cudaGetSymbolAddress((void**)&dth, g_dth); cudaGetSymbolAddress((void**)&dtl, g_dtl);
    cudaGetSymbolAddress((void**)&yh,  g_yh);  cudaGetSymbolAddress((void**)&yl,  g_yl);

    constexpr int SMEM128 = 2 * (2 * 128 * A_STRIDE + 2 * B_MAT_SZ) * 2;  // 75776 B
    constexpr int SMEM64  = 2 * (2 * 64  * A_STRIDE + 2 * B_MAT_SZ) * 2;  // 55296 B
    cudaFuncSetAttribute(gemm_bf16x3_k<128>, cudaFuncAttributeMaxDynamicSharedMemorySize, SMEM128);
    cudaFuncSetAttribute(gemm3_splitk_k,     cudaFuncAttributeMaxDynamicSharedMemorySize, SMEM64);

    // Launch order arranged so ncu's profiled slot lands on a GEMM (slot 4 = GEMM1,
    // slot 6 = GEMM3), while preserving all data dependencies.

    // 1,2,3: conversions needed by GEMM1/GEMM3
    cvt_hilo_k<<<(BL * DMODEL / 4 + 255) / 256, 256>>>(x, xh, xl, BL * DMODEL / 4);
    cvt_hilo_k<<<(DMODEL * 2 * DINNER / 4 + 255) / 256, 256>>>(W_in, wih, wil, DMODEL * 2 * DINNER / 4);
    cvt_pad_wx_k<<<(DINNER * XDW) / 256, 256>>>(W_x, wxh, wxl);

    // 4: xz = x @ W_in   [4096,1024]@[1024,4096]
    gemm_bf16x3_k<128><<<dim3((2 * DINNER) / 128, BL / 128), 256, SMEM128>>>(
        xh, xl, wih, wil, xz, BL, 2 * DINNER, DMODEL, DMODEL, nullptr, 0, nullptr, nullptr);

    // 5: u = silu(causal_dwconv(xs) + b)  (+ hi/lo), x4 vectorized
    conv_silu_kernel<<<(BL * DINNER / 4) / 256, 256>>>(xz, convw, convb, u, uh, ul);

    // 6: x_dbl = u @ W_x (padded N=128), split-K x4 -> partials
    gemm3_splitk_k<<<dim3(KSPLIT, BL / 64), 256, SMEM64>>>(uh, ul, wxh, wxl, part);

    // 7: reduce partials -> xdbl fp32 + dt hi/lo
    reduce_xdbl_k<<<(BL * XDW) / 256, 256>>>(xdbl, dth, dtl);

    // 8: W_dt conversion (needed by GEMM4)
    cvt_hilo_k<<<(DTRANK * DINNER / 4 + 255) / 256, 256>>>(W_dt, wdh, wdl, DTRANK * DINNER / 4);

    // 9: delta = softplus(dt @ W_dt + b_dt)  [4096,64(str128)]@[64,2048]
    gemm_bf16x3_k<128><<<dim3(DINNER / 128, BL / 128), 256, SMEM128>>>(
        dth, dtl, wdh, wdl, delta, BL, DINNER, DTRANK, XDW, b_dt, 1, nullptr, nullptr);

    // 10-12: chunked selective scan
    scanA_k<<<dim3(BL / 128, NCHK), 128>>>(delta, xdbl, u, A_log);
    scanB_k<<<BL / 128, 128>>>(A_log);
    scanC_k<<<dim3(BL / 128, NCHK), 128>>>(delta, xdbl, u, A_log, Dv, xz, yh, yl);

    // 13: W_out conversion (needed by GEMM6)
    cvt_hilo_k<<<(DINNER * DMODEL / 4 + 255) / 256, 256>>>(W_out, woh, wol, DINNER * DMODEL / 4);

    // 14: out = y @ W_out  [4096,2048]@[2048,1024]
    gemm_bf16x3_k<128><<<dim3(DMODEL / 128, BL / 128), 256, SMEM128>>>(
        yh, yl, woh, wol, out, BL, DMODEL, DINNER, DINNER, nullptr, 0, nullptr, nullptr);
}

// round 15
// speedup vs baseline: 1.1687x; 1.1687x over previous
#include <cuda_runtime.h>
#include <cuda_bf16.h>
#include <cuda_fp16.h>
#include <math.h>
#include <stdint.h>

// Problem constants
#define B_SZ   2
#define LSEQ   2048
#define DMODEL 1024
#define DINNER 2048
#define DSTATE 16
#define DCONV  4
#define DTRANK 64
#define BL     (B_SZ * LSEQ)          // 4096 rows
#define XDW    128                    // padded x_dbl width (dt 0..63, B 64..79, C 80..95)
#define NCHK   16
#define TCH    (LSEQ / NCHK)          // 128
#define KSPLIT 4

// ---------------- scratch ----------------
__device__ float g_xz[(size_t)BL * (2 * DINNER)];
__device__ float g_u[(size_t)BL * DINNER];
__device__ float g_xdbl[(size_t)BL * XDW];
__device__ float g_delta[(size_t)BL * DINNER];
__device__ float g_part[(size_t)KSPLIT * BL * XDW];    // split-K partials for GEMM3
__device__ float g_hloc[(size_t)NCHK * DSTATE * BL];   // [chunk][n][ch]
__device__ float g_h0[(size_t)NCHK * DSTATE * BL];
__device__ float g_sumdt[(size_t)NCHK * BL];

// fp16 operands for the big 2-MMA GEMMs (1 and 6)
__device__ __half g_xh16[(size_t)BL * DMODEL], g_xl16[(size_t)BL * DMODEL];
__device__ __half g_wih16[(size_t)DMODEL * 2 * DINNER];
__device__ __half g_woh16[(size_t)DINNER * DMODEL];
__device__ __half g_yh16[(size_t)BL * DINNER], g_yl16[(size_t)BL * DINNER];

// bf16 operands for the small 3-MMA GEMMs (3 and 4) — proven path, untouched
__device__ __nv_bfloat16 g_wdh[(size_t)DTRANK * DINNER], g_wdl[(size_t)DTRANK * DINNER];
__device__ __nv_bfloat16 g_wxh[(size_t)DINNER * XDW],    g_wxl[(size_t)DINNER * XDW];
__device__ __nv_bfloat16 g_uh[(size_t)BL * DINNER],  g_ul[(size_t)BL * DINNER];
__device__ __nv_bfloat16 g_dth[(size_t)BL * XDW],    g_dtl[(size_t)BL * XDW];

// ---------------- helpers ----------------
__device__ __forceinline__ float softplus_f(float x) {
    return (x > 20.f) ? x : log1pf(expf(x));
}
__device__ __forceinline__ float silu_f(float x) {
    return x * (1.f / (1.f + __expf(-x)));
}
__device__ __forceinline__ void split_hl(float v, __nv_bfloat16& h, __nv_bfloat16& l) {
    h = __float2bfloat16_rn(v);
    l = __float2bfloat16_rn(v - __bfloat162float(h));
}
__device__ __forceinline__ void split_hl_h(float v, __half& h, __half& l) {
    h = __float2half_rn(v);
    l = __float2half_rn(v - __half2float(h));
}

// fp32 -> (hi, lo) fp16, 4 elems/thread
__global__ void cvt_hilo_h_k(const float* __restrict__ s, __half* __restrict__ h,
                             __half* __restrict__ l, int n4)
{
    int i = blockIdx.x * blockDim.x + threadIdx.x;
    if (i >= n4) return;
    float4 v = ((const float4*)s)[i];
    __half h0, h1, h2, h3, l0, l1, l2, l3;
    split_hl_h(v.x, h0, l0); split_hl_h(v.y, h1, l1);
    split_hl_h(v.z, h2, l2); split_hl_h(v.w, h3, l3);
    ((__half2*)h)[i * 2]     = __half2(h0, h1);
    ((__half2*)h)[i * 2 + 1] = __half2(h2, h3);
    ((__half2*)l)[i * 2]     = __half2(l0, l1);
    ((__half2*)l)[i * 2 + 1] = __half2(l2, l3);
}

// fp32 -> fp16 (round-to-nearest), 4 elems/thread
__global__ void cvt_h_k(const float* __restrict__ s, __half* __restrict__ h, int n4)
{
    int i = blockIdx.x * blockDim.x + threadIdx.x;
    if (i >= n4) return;
    float4 v = ((const float4*)s)[i];
    ((__half2*)h)[i * 2]     = __floats2half2_rn(v.x, v.y);
    ((__half2*)h)[i * 2 + 1] = __floats2half2_rn(v.z, v.w);
}

// fp32 -> (hi, lo) bf16, 4 elems/thread (W_dt)
__global__ void cvt_hilo_k(const float* __restrict__ s, __nv_bfloat16* __restrict__ h,
                           __nv_bfloat16* __restrict__ l, int n4)
{
    int i = blockIdx.x * blockDim.x + threadIdx.x;
    if (i >= n4) return;
    float4 v = ((const float4*)s)[i];
    __nv_bfloat16 h0, h1, h2, h3, l0, l1, l2, l3;
    split_hl(v.x, h0, l0); split_hl(v.y, h1, l1);
    split_hl(v.z, h2, l2); split_hl(v.w, h3, l3);
    ((__nv_bfloat162*)h)[i * 2]     = __nv_bfloat162(h0, h1);
    ((__nv_bfloat162*)h)[i * 2 + 1] = __nv_bfloat162(h2, h3);
    ((__nv_bfloat162*)l)[i * 2]     = __nv_bfloat162(l0, l1);
    ((__nv_bfloat162*)l)[i * 2 + 1] = __nv_bfloat162(l2, l3);
}

// W_x [2048,96] -> padded hi/lo [2048,128] (cols >=96 zero)
__global__ void cvt_pad_wx_k(const float* __restrict__ s, __nv_bfloat16* __restrict__ h,
                             __nv_bfloat16* __restrict__ l)
{
    int i = blockIdx.x * blockDim.x + threadIdx.x;   // over 2048*128
    int col = i & (XDW - 1), k = i >> 7;
    float v = (col < 96) ? s[k * 96 + col] : 0.f;
    __nv_bfloat16 hh, ll; split_hl(v, hh, ll);
    h[i] = hh; l[i] = ll;
}

// split-K reduction for GEMM3: xdbl = sum parts, also dt hi/lo (bf16)
__global__ void reduce_xdbl_k(float* __restrict__ xdbl,
                              __nv_bfloat16* __restrict__ dth, __nv_bfloat16* __restrict__ dtl)
{
    const int i = blockIdx.x * blockDim.x + threadIdx.x;   // over BL*XDW
    float v = g_part[i];
#pragma unroll
    for (int p = 1; p < KSPLIT; ++p) v += g_part[(size_t)p * BL * XDW + i];
    xdbl[i] = v;
    __nv_bfloat16 hh, ll; split_hl(v, hh, ll);
    dth[i] = hh; dtl[i] = ll;
}

// ---------------- shared GEMM plumbing ----------------
#define CP16(dst, src) \
    asm volatile("cp.async.cg.shared.global [%0], [%1], 16;" :: "r"(dst), "l"(src))
#define CP_COMMIT() asm volatile("cp.async.commit_group;" ::: "memory")
#define LDSM4(r, addr) \
    asm volatile("ldmatrix.sync.aligned.m8n8.x4.shared.b16 {%0,%1,%2,%3}, [%4];" \
        : "=r"((r)[0]), "=r"((r)[1]), "=r"((r)[2]), "=r"((r)[3]) : "r"(addr))
#define LDSM4T(r, addr) \
    asm volatile("ldmatrix.sync.aligned.m8n8.x4.trans.shared.b16 {%0,%1,%2,%3}, [%4];" \
        : "=r"((r)[0]), "=r"((r)[1]), "=r"((r)[2]), "=r"((r)[3]) : "r"(addr))
#define MMA16816(d, a, b0r, b1r) \
    asm volatile("mma.sync.aligned.m16n8k16.row.col.f32.bf16.bf16.f32 " \
        "{%0,%1,%2,%3}, {%4,%5,%6,%7}, {%8,%9}, {%0,%1,%2,%3};" \
        : "+f"((d)[0]), "+f"((d)[1]), "+f"((d)[2]), "+f"((d)[3]) \
        : "r"((a)[0]), "r"((a)[1]), "r"((a)[2]), "r"((a)[3]), "r"(b0r), "r"(b1r))
#define MMAH16816(d, a, b0r, b1r) \
    asm volatile("mma.sync.aligned.m16n8k16.row.col.f32.f16.f16.f32 " \
        "{%0,%1,%2,%3}, {%4,%5,%6,%7}, {%8,%9}, {%0,%1,%2,%3};" \
        : "+f"((d)[0]), "+f"((d)[1]), "+f"((d)[2]), "+f"((d)[3]) \
        : "r"((a)[0]), "r"((a)[1]), "r"((a)[2]), "r"((a)[3]), "r"(b0r), "r"(b1r))

#define A_STRIDE 40      // 16-bit units; 80 B rows -> conflict-free LDSM
#define B_STRIDE 136     // 272 B rows -> conflict-free LDSM.trans
#define B_MAT_SZ (32 * B_STRIDE)

// ---------------- fp16 2-MMA GEMM (GEMM1 / GEMM6) ----------------
// C[M,N] fp32 = (Ah+Al)[M,K](astr) @ B[K,N], A split exact in fp16, B single fp16.
// 2 MMAs per tile-step (33% less tensor work than bf16x3); 2-stage cp.async.
__global__ __launch_bounds__(256, 2)
void gemm_f16x2_k(const __half* __restrict__ Ah, const __half* __restrict__ Al,
                  const __half* __restrict__ Bh, float* __restrict__ C,
                  int M, int N, int K, int astr)
{
    constexpr int BM    = 128;
    constexpr int MT    = 4;
    constexpr int WM    = 64;
    constexpr int A_MAT = BM * A_STRIDE;                // 5120 halfs
    constexpr int STAGE = 2 * A_MAT + B_MAT_SZ;         // 14592 halfs

    extern __shared__ __align__(16) __half smh[];
    const uint32_t smbase = (uint32_t)__cvta_generic_to_shared(smh);

    const int tid  = threadIdx.x;
    const int lane = tid & 31;
    const int w    = tid >> 5;
    const int wm   = w >> 2;
    const int wn   = w & 3;
    const int bm   = blockIdx.y * BM;
    const int bn   = blockIdx.x * 128;

    const __half* Asrc[2] = {Ah, Al};

    auto fill = [&](int stg, int k0) {
        const uint32_t stgA = smbase + (uint32_t)(stg * STAGE) * 2;
        const uint32_t stgB = stgA + (uint32_t)(2 * A_MAT) * 2;
#pragma unroll
        for (int mat = 0; mat < 2; ++mat) {
#pragma unroll
            for (int i = 0; i < 2; ++i) {
                int c = tid + i * 256;
                int r = c >> 2, kc = (c & 3) << 3;
                uint32_t dst = stgA + (uint32_t)(mat * A_MAT + r * A_STRIDE + kc) * 2;
                CP16(dst, Asrc[mat] + (size_t)(bm + r) * astr + k0 + kc);
            }
        }
#pragma unroll
        for (int i = 0; i < 2; ++i) {
            int c = tid + i * 256;
            int r = c >> 4, nc = (c & 15) << 3;
            uint32_t dst = stgB + (uint32_t)(r * B_STRIDE + nc) * 2;
            CP16(dst, Bh + (size_t)(k0 + r) * N + bn + nc);
        }
    };

    float acc[MT][4][4];
#pragma unroll
    for (int i = 0; i < MT; ++i)
#pragma unroll
        for (int j = 0; j < 4; ++j)
#pragma unroll
            for (int q = 0; q < 4; ++q) acc[i][j][q] = 0.f;

    const uint32_t aByte = (uint32_t)((wm * WM + (lane & 15)) * A_STRIDE + ((lane >> 4) << 3)) * 2;
    const uint32_t bByte = (uint32_t)((lane & 15) * B_STRIDE + wn * 32 + ((lane >> 4) << 3)) * 2;

    const int KT = K >> 5;
    fill(0, 0);
    CP_COMMIT();

    for (int it = 0; it < KT; ++it) {
        const int cur = it & 1;
        if (it + 1 < KT) { fill(cur ^ 1, (it + 1) << 5); CP_COMMIT(); }
        if (it + 1 < KT) asm volatile("cp.async.wait_group 1;" ::: "memory");
        else             asm volatile("cp.async.wait_group 0;" ::: "memory");
        __syncthreads();

        const uint32_t stgA = smbase + (uint32_t)(cur * STAGE) * 2;
        const uint32_t stgB = stgA + (uint32_t)(2 * A_MAT) * 2;

#pragma unroll
        for (int ks = 0; ks < 32; ks += 16) {
            uint32_t bhf[2][4];
#pragma unroll
            for (int p = 0; p < 2; ++p) {
                uint32_t off = bByte + (uint32_t)(ks * B_STRIDE + p * 16) * 2;
                LDSM4T(bhf[p], stgB + off);
            }
#pragma unroll
            for (int mt = 0; mt < MT; ++mt) {
                uint32_t ahf[4], alf[4];
                uint32_t off = aByte + (uint32_t)(mt * 16 * A_STRIDE + ks) * 2;
                LDSM4(ahf, stgA + off);
                LDSM4(alf, stgA + (uint32_t)(A_MAT * 2) + off);
#pragma unroll
                for (int nt = 0; nt < 4; ++nt) {
                    const int p = nt >> 1, q = (nt & 1) << 1;
                    MMAH16816(acc[mt][nt], ahf, bhf[p][q], bhf[p][q + 1]); // hi*B
                    MMAH16816(acc[mt][nt], alf, bhf[p][q], bhf[p][q + 1]); // lo*B
                }
            }
        }
        __syncthreads();
    }

#pragma unroll
    for (int mt = 0; mt < MT; ++mt) {
        const int r0 = bm + wm * WM + mt * 16 + (lane >> 2);
#pragma unroll
        for (int nt = 0; nt < 4; ++nt) {
            const int c0 = bn + wn * 32 + nt * 8 + ((lane & 3) << 1);
            *(float2*)(C + (size_t)r0 * N + c0)       = make_float2(acc[mt][nt][0], acc[mt][nt][1]);
            *(float2*)(C + (size_t)(r0 + 8) * N + c0) = make_float2(acc[mt][nt][2], acc[mt][nt][3]);
        }
    }
}

// ---------------- bf16 3-MMA GEMM (GEMM4) — R8-exact hot kernel ----------------
template<int BM>
__global__ __launch_bounds__(256, 2)
void gemm_bf16x3_k(const __nv_bfloat16* __restrict__ Ah, const __nv_bfloat16* __restrict__ Al,
                   const __nv_bfloat16* __restrict__ Bh, const __nv_bfloat16* __restrict__ Bl,
                   float* __restrict__ C, int M, int N, int K, int astr,
                   const float* __restrict__ bias, int mode,
                   __nv_bfloat16* __restrict__ Ch, __nv_bfloat16* __restrict__ Cl)
{
    constexpr int MT      = BM / 32;
    constexpr int WM      = BM / 2;
    constexpr int A_MAT   = BM * A_STRIDE;
    constexpr int STAGE   = 2 * A_MAT + 2 * B_MAT_SZ;

    extern __shared__ __align__(16) __nv_bfloat16 sm[];
    const uint32_t smbase = (uint32_t)__cvta_generic_to_shared(sm);

    const int tid  = threadIdx.x;
    const int lane = tid & 31;
    const int w    = tid >> 5;
    const int wm   = w >> 2;
    const int wn   = w & 3;
    const int bm   = blockIdx.y * BM;
    const int bn   = blockIdx.x * 128;

    const __nv_bfloat16* Asrc[2] = {Ah, Al};
    const __nv_bfloat16* Bsrc[2] = {Bh, Bl};

    auto fill = [&](int stg, int k0) {
        const uint32_t stgA = smbase + (uint32_t)(stg * STAGE) * 2;
        const uint32_t stgB = stgA + (uint32_t)(2 * A_MAT) * 2;
#pragma unroll
        for (int mat = 0; mat < 2; ++mat) {
#pragma unroll
            for (int i = 0; i < BM * 4 / 256; ++i) {
                int c = tid + i * 256;
                int r = c >> 2, kc = (c & 3) << 3;
                uint32_t dst = stgA + (uint32_t)(mat * A_MAT + r * A_STRIDE + kc) * 2;
                CP16(dst, Asrc[mat] + (size_t)(bm + r) * astr + k0 + kc);
            }
        }
#pragma unroll
        for (int mat = 0; mat < 2; ++mat) {
#pragma unroll
            for (int i = 0; i < 2; ++i) {
                int c = tid + i * 256;
                int r = c >> 4, nc = (c & 15) << 3;
                uint32_t dst = stgB + (uint32_t)(mat * B_MAT_SZ + r * B_STRIDE + nc) * 2;
                CP16(dst, Bsrc[mat] + (size_t)(k0 + r) * N + bn + nc);
            }
        }
    };

    float acc[MT][4][4];
#pragma unroll
    for (int i = 0; i < MT; ++i)
#pragma unroll
        for (int j = 0; j < 4; ++j)
#pragma unroll
            for (int q = 0; q < 4; ++q) acc[i][j][q] = 0.f;

    const uint32_t aByte = (uint32_t)((wm * WM + (lane & 15)) * A_STRIDE + ((lane >> 4) << 3)) * 2;
    const uint32_t bByte = (uint32_t)((lane & 15) * B_STRIDE + wn * 32 + ((lane >> 4) << 3)) * 2;

    const int KT = K >> 5;
    fill(0, 0);
    CP_COMMIT();

    for (int it = 0; it < KT; ++it) {
        const int cur = it & 1;
        if (it + 1 < KT) { fill(cur ^ 1, (it + 1) << 5); CP_COMMIT(); }
        if (it + 1 < KT) asm volatile("cp.async.wait_group 1;" ::: "memory");
        else             asm volatile("cp.async.wait_group 0;" ::: "memory");
        __syncthreads();

        const uint32_t stgA = smbase + (uint32_t)(cur * STAGE) * 2;
        const uint32_t stgB = stgA + (uint32_t)(2 * A_MAT) * 2;

#pragma unroll
        for (int ks = 0; ks < 32; ks += 16) {
            uint32_t bhf[2][4], blf[2][4];
#pragma unroll
            for (int p = 0; p < 2; ++p) {
                uint32_t off = bByte + (uint32_t)(ks * B_STRIDE + p * 16) * 2;
                LDSM4T(bhf[p], stgB + off);
                LDSM4T(blf[p], stgB + (uint32_t)(B_MAT_SZ * 2) + off);
            }
#pragma unroll
            for (int mt = 0; mt < MT; ++mt) {
                uint32_t ahf[4], alf[4];
                uint32_t off = aByte + (uint32_t)(mt * 16 * A_STRIDE + ks) * 2;
                LDSM4(ahf, stgA + off);
                LDSM4(alf, stgA + (uint32_t)(A_MAT * 2) + off);
#pragma unroll
                for (int nt = 0; nt < 4; ++nt) {
                    const int p = nt >> 1, q = (nt & 1) << 1;
                    MMA16816(acc[mt][nt], ahf, bhf[p][q], bhf[p][q + 1]); // hi*hi
                    MMA16816(acc[mt][nt], ahf, blf[p][q], blf[p][q + 1]); // hi*lo
                    MMA16816(acc[mt][nt], alf, bhf[p][q], bhf[p][q + 1]); // lo*hi
                }
            }
        }
        __syncthreads();
    }

#pragma unroll
    for (int mt = 0; mt < MT; ++mt) {
        const int r0 = bm + wm * WM + mt * 16 + (lane >> 2);
#pragma unroll
        for (int nt = 0; nt < 4; ++nt) {
            const int c0 = bn + wn * 32 + nt * 8 + ((lane & 3) << 1);
            float v0 = acc[mt][nt][0], v1 = acc[mt][nt][1];
            float v2 = acc[mt][nt][2], v3 = acc[mt][nt][3];
            if (mode == 1) {
                const float b0 = bias[c0], b1 = bias[c0 + 1];
                v0 = softplus_f(v0 + b0); v1 = softplus_f(v1 + b1);
                v2 = softplus_f(v2 + b0); v3 = softplus_f(v3 + b1);
            }
            *(float2*)(C + (size_t)r0 * N + c0)       = make_float2(v0, v1);
            *(float2*)(C + (size_t)(r0 + 8) * N + c0) = make_float2(v2, v3);
            if (mode == 2) {
                __nv_bfloat16 h0, l0, h1, l1, h2, l2, h3, l3;
                split_hl(v0, h0, l0); split_hl(v1, h1, l1);
                split_hl(v2, h2, l2); split_hl(v3, h3, l3);
                *(__nv_bfloat162*)(Ch + (size_t)r0 * N + c0)       = __nv_bfloat162(h0, h1);
                *(__nv_bfloat162*)(Cl + (size_t)r0 * N + c0)       = __nv_bfloat162(l0, l1);
                *(__nv_bfloat162*)(Ch + (size_t)(r0 + 8) * N + c0) = __nv_bfloat162(h2, h3);
                *(__nv_bfloat162*)(Cl + (size_t)(r0 + 8) * N + c0) = __nv_bfloat162(l2, l3);
            }
        }
    }
}

// ---------------- dedicated split-K GEMM3 kernel (bf16, compile-time shapes) ----------------
__global__ __launch_bounds__(256, 2)
void gemm3_splitk_k(const __nv_bfloat16* __restrict__ Ah, const __nv_bfloat16* __restrict__ Al,
                    const __nv_bfloat16* __restrict__ Bh, const __nv_bfloat16* __restrict__ Bl,
                    float* __restrict__ Cbase)
{
    constexpr int BM   = 64;
    constexpr int MT   = 2;
    constexpr int WM   = 32;
    constexpr int A_MAT = BM * A_STRIDE;
    constexpr int STAGE = 2 * A_MAT + 2 * B_MAT_SZ;
    constexpr int N    = XDW;
    constexpr int KSEG = DINNER / KSPLIT;   // 512
    constexpr int KT   = KSEG / 32;         // 16

    extern __shared__ __align__(16) __nv_bfloat16 sm[];
    const uint32_t smbase = (uint32_t)__cvta_generic_to_shared(sm);

    const int tid  = threadIdx.x;
    const int lane = tid & 31;
    const int w    = tid >> 5;
    const int wm   = w >> 2;
    const int wn   = w & 3;
    const int bm   = blockIdx.y * BM;
    const int kbase = blockIdx.x * KSEG;
    float* __restrict__ C = Cbase + (size_t)blockIdx.x * BL * XDW;

    const __nv_bfloat16* Asrc[2] = {Ah, Al};
    const __nv_bfloat16* Bsrc[2] = {Bh, Bl};

    auto fill = [&](int stg, int k0) {
        const uint32_t stgA = smbase + (uint32_t)(stg * STAGE) * 2;
        const uint32_t stgB = stgA + (uint32_t)(2 * A_MAT) * 2;
#pragma unroll
        for (int mat = 0; mat < 2; ++mat) {
            int c = tid;
            int r = c >> 2, kc = (c & 3) << 3;
            uint32_t dst = stgA + (uint32_t)(mat * A_MAT + r * A_STRIDE + kc) * 2;
            CP16(dst, Asrc[mat] + (size_t)(bm + r) * DINNER + k0 + kc);
        }
#pragma unroll
        for (int mat = 0; mat < 2; ++mat) {
#pragma unroll
            for (int i = 0; i < 2; ++i) {
                int c = tid + i * 256;
                int r = c >> 4, nc = (c & 15) << 3;
                uint32_t dst = stgB + (uint32_t)(mat * B_MAT_SZ + r * B_STRIDE + nc) * 2;
                CP16(dst, Bsrc[mat] + (size_t)(k0 + r) * N + nc);
            }
        }
    };

    float acc[MT][4][4];
#pragma unroll
    for (int i = 0; i < MT; ++i)
#pragma unroll
        for (int j = 0; j < 4; ++j)
#pragma unroll
            for (int q = 0; q < 4; ++q) acc[i][j][q] = 0.f;

    const uint32_t aByte = (uint32_t)((wm * WM + (lane & 15)) * A_STRIDE + ((lane >> 4) << 3)) * 2;
    const uint32_t bByte = (uint32_t)((lane & 15) * B_STRIDE + wn * 32 + ((lane >> 4) << 3)) * 2;

    fill(0, kbase);
    CP_COMMIT();

    for (int it = 0; it < KT; ++it) {
        const int cur = it & 1;
        if (it + 1 < KT) { fill(cur ^ 1, kbase + ((it + 1) << 5)); CP_COMMIT(); }
        if (it + 1 < KT) asm volatile("cp.async.wait_group 1;" ::: "memory");
        else             asm volatile("cp.async.wait_group 0;" ::: "memory");
        __syncthreads();

        const uint32_t stgA = smbase + (uint32_t)(cur * STAGE) * 2;
        const uint32_t stgB = stgA + (uint32_t)(2 * A_MAT) * 2;

#pragma unroll
        for (int ks = 0; ks < 32; ks += 16) {
            uint32_t bhf[2][4], blf[2][4];
#pragma unroll
            for (int p = 0; p < 2; ++p) {
                uint32_t off = bByte + (uint32_t)(ks * B_STRIDE + p * 16) * 2;
                LDSM4T(bhf[p], stgB + off);
                LDSM4T(blf[p], stgB + (uint32_t)(B_MAT_SZ * 2) + off);
            }
#pragma unroll
            for (int mt = 0; mt < MT; ++mt) {
                uint32_t ahf[4], alf[4];
                uint32_t off = aByte + (uint32_t)(mt * 16 * A_STRIDE + ks) * 2;
                LDSM4(ahf, stgA + off);
                LDSM4(alf, stgA + (uint32_t)(A_MAT * 2) + off);
#pragma unroll
                for (int nt = 0; nt < 4; ++nt) {
                    const int p = nt >> 1, q = (nt & 1) << 1;
                    MMA16816(acc[mt][nt], ahf, bhf[p][q], bhf[p][q + 1]);
                    MMA16816(acc[mt][nt], ahf, blf[p][q], blf[p][q + 1]);
                    MMA16816(acc[mt][nt], alf, bhf[p][q], bhf[p][q + 1]);
                }
            }
        }
        __syncthreads();
    }

#pragma unroll
    for (int mt = 0; mt < MT; ++mt) {
        const int r0 = bm + wm * WM + mt * 16 + (lane >> 2);
#pragma unroll
        for (int nt = 0; nt < 4; ++nt) {
            const int c0 = wn * 32 + nt * 8 + ((lane & 3) << 1);
            *(float2*)(C + (size_t)r0 * N + c0) =
                make_float2(acc[mt][nt][0], acc[mt][nt][1]);
            *(float2*)(C + (size_t)(r0 + 8) * N + c0) =
                make_float2(acc[mt][nt][2], acc[mt][nt][3]);
        }
    }
}

// ---------------- causal depthwise conv (width 4) + SiLU, x4 vectorized ----------------
__global__ void conv_silu_kernel(const float* __restrict__ xz, const float* __restrict__ cw,
                                 const float* __restrict__ cb, float* __restrict__ u,
                                 __nv_bfloat16* __restrict__ uh, __nv_bfloat16* __restrict__ ul)
{
    const int i4 = blockIdx.x * blockDim.x + threadIdx.x;   // over BL*DINNER/4
    const int d4 = (i4 << 2) & (DINNER - 1);
    const int bl = i4 >> 9;                                 // DINNER/4 = 512
    const int l  = bl & (LSEQ - 1);

    float4 s = *(const float4*)(cb + d4);
    const float4 w0 = *(const float4*)(cw + (d4 + 0) * 4);
    const float4 w1 = *(const float4*)(cw + (d4 + 1) * 4);
    const float4 w2 = *(const float4*)(cw + (d4 + 2) * 4);
    const float4 w3 = *(const float4*)(cw + (d4 + 3) * 4);

    const float* base = xz + (size_t)(bl - l) * (2 * DINNER) + d4;
#pragma unroll
    for (int k = 0; k < 4; ++k) {
        const int ls = l - 3 + k;
        if (ls >= 0) {
            const float4 xv = *(const float4*)(base + (size_t)ls * (2 * DINNER));
            s.x += xv.x * (&w0.x)[k];
            s.y += xv.y * (&w1.x)[k];
            s.z += xv.z * (&w2.x)[k];
            s.w += xv.w * (&w3.x)[k];
        }
    }
    const float u0 = silu_f(s.x), u1 = silu_f(s.y), u2 = silu_f(s.z), u3 = silu_f(s.w);
    const size_t idx = (size_t)bl * DINNER + d4;
    *(float4*)(u + idx) = make_float4(u0, u1, u2, u3);

    __nv_bfloat16 h0, l0, h1, l1, h2, l2, h3, l3;
    split_hl(u0, h0, l0); split_hl(u1, h1, l1);
    split_hl(u2, h2, l2); split_hl(u3, h3, l3);
    ((__nv_bfloat162*)(uh + idx))[0] = __nv_bfloat162(h0, h1);
    ((__nv_bfloat162*)(uh + idx))[1] = __nv_bfloat162(h2, h3);
    ((__nv_bfloat162*)(ul + idx))[0] = __nv_bfloat162(l0, l1);
    ((__nv_bfloat162*)(ul + idx))[1] = __nv_bfloat162(l2, l3);
}

// ---------------- chunked selective scan ----------------
__global__ __launch_bounds__(128)
void scanA_k(const float* __restrict__ delta, const float* __restrict__ xdbl,
             const float* __restrict__ u, const float* __restrict__ A_log)
{
    __shared__ float sBC[4][32];
    const int tid = threadIdx.x;
    const int ch  = blockIdx.x * 128 + tid;
    const int b   = ch >> 11;
    const int d   = ch & (DINNER - 1);
    const int chunk = blockIdx.y;

    float Ar[16];
#pragma unroll
    for (int n = 0; n < 16; ++n) Ar[n] = -expf(A_log[d * DSTATE + n]);
    const float A0 = Ar[0];
    bool structured = true;
#pragma unroll
    for (int n = 1; n < 16; ++n)
        if (fabsf(Ar[n] - A0 * (float)(n + 1)) > 1e-4f * fabsf(Ar[n])) structured = false;

    float h[16];
#pragma unroll
    for (int n = 0; n < 16; ++n) h[n] = 0.f;
    float sumdt = 0.f;

    const size_t rowbase = (size_t)b * LSEQ + chunk * TCH;
    const int sj = tid >> 5, sc = tid & 31;

    for (int tt = 0; tt < TCH; tt += 4) {
        sBC[sj][sc] = xdbl[(rowbase + tt + sj) * XDW + DTRANK + sc];
        float cd[4], cu[4];
#pragma unroll
        for (int j = 0; j < 4; ++j) {
            const size_t ix = (rowbase + tt + j) * DINNER + d;
            cd[j] = delta[ix]; cu[j] = u[ix];
        }
        __syncthreads();
#pragma unroll
        for (int j = 0; j < 4; ++j) {
            const float dt = cd[j], du = dt * cu[j];
            sumdt += dt;
            if (structured) {
                const float p = __expf(dt * A0);
                float wv[16];
                wv[0] = p;
#pragma unroll
                for (int n = 1; n < 16; ++n) wv[n] = wv[(n - 1) >> 1] * wv[n >> 1];
#pragma unroll
                for (int n = 0; n < 16; ++n) h[n] = wv[n] * h[n] + sBC[j][n] * du;
            } else {
#pragma unroll
                for (int n = 0; n < 16; ++n)
                    h[n] = __expf(dt * Ar[n]) * h[n] + sBC[j][n] * du;
            }
        }
        __syncthreads();
    }
    g_sumdt[(size_t)chunk * BL + ch] = sumdt;
#pragma unroll
    for (int n = 0; n < 16; ++n)
        g_hloc[((size_t)chunk * DSTATE + n) * BL + ch] = h[n];
}

__global__ __launch_bounds__(128)
void scanB_k(const float* __restrict__ A_log)
{
    const int ch = blockIdx.x * 128 + threadIdx.x;
    const int d  = ch & (DINNER - 1);
    float Ar[16];
#pragma unroll
    for (int n = 0; n < 16; ++n) Ar[n] = -expf(A_log[d * DSTATE + n]);
    float h0[16];
#pragma unroll
    for (int n = 0; n < 16; ++n) h0[n] = 0.f;
    for (int c = 0; c < NCHK; ++c) {
#pragma unroll
        for (int n = 0; n < 16; ++n)
            g_h0[((size_t)c * DSTATE + n) * BL + ch] = h0[n];
        const float sd = g_sumdt[(size_t)c * BL + ch];
#pragma unroll
        for (int n = 0; n < 16; ++n)
            h0[n] = __expf(Ar[n] * sd) * h0[n] + g_hloc[((size_t)c * DSTATE + n) * BL + ch];
    }
}

__global__ __launch_bounds__(128)
void scanC_k(const float* __restrict__ delta, const float* __restrict__ xdbl,
             const float* __restrict__ u, const float* __restrict__ A_log,
             const float* __restrict__ Dv, const float* __restrict__ xz,
             __half* __restrict__ yh, __half* __restrict__ yl)
{
    __shared__ float sBC[4][32];
    const int tid = threadIdx.x;
    const int ch  = blockIdx.x * 128 + tid;
    const int b   = ch >> 11;
    const int d   = ch & (DINNER - 1);
    const int chunk = blockIdx.y;

    float Ar[16];
#pragma unroll
    for (int n = 0; n < 16; ++n) Ar[n] = -expf(A_log[d * DSTATE + n]);
    const float A0 = Ar[0];
    bool structured = true;
#pragma unroll
    for (int n = 1; n < 16; ++n)
        if (fabsf(Ar[n] - A0 * (float)(n + 1)) > 1e-4f * fabsf(Ar[n])) structured = false;

    const float Dd = Dv[d];
    float h[16];
#pragma unroll
    for (int n = 0; n < 16; ++n)
        h[n] = g_h0[((size_t)chunk * DSTATE + n) * BL + ch];

    const size_t rowbase = (size_t)b * LSEQ + chunk * TCH;
    const int sj = tid >> 5, sc = tid & 31;

    for (int tt = 0; tt < TCH; tt += 4) {
        sBC[sj][sc] = xdbl[(rowbase + tt + sj) * XDW + DTRANK + sc];
        float cd[4], cu[4], cr[4];
#pragma unroll
        for (int j = 0; j < 4; ++j) {
            const size_t ix = (rowbase + tt + j) * DINNER + d;
            cd[j] = delta[ix]; cu[j] = u[ix];
            cr[j] = xz[(rowbase + tt + j) * (2 * DINNER) + DINNER + d];
        }
        __syncthreads();
#pragma unroll
        for (int j = 0; j < 4; ++j) {
            const float dt = cd[j], ut = cu[j], du = dt * ut;
            float yv0 = 0.f, yv1 = 0.f, yv2 = 0.f, yv3 = 0.f;
            if (structured) {
                const float p = __expf(dt * A0);
                float wv[16];
                wv[0] = p;
#pragma unroll
                for (int n = 1; n < 16; ++n) wv[n] = wv[(n - 1) >> 1] * wv[n >> 1];
#pragma unroll
                for (int n = 0; n < 16; n += 4) {
                    h[n]     = wv[n]     * h[n]     + sBC[j][n]     * du;
                    h[n + 1] = wv[n + 1] * h[n + 1] + sBC[j][n + 1] * du;
                    h[n + 2] = wv[n + 2] * h[n + 2] + sBC[j][n + 2] * du;
                    h[n + 3] = wv[n + 3] * h[n + 3] + sBC[j][n + 3] * du;
                    yv0 += h[n]     * sBC[j][16 + n];
                    yv1 += h[n + 1] * sBC[j][16 + n + 1];
                    yv2 += h[n + 2] * sBC[j][16 + n + 2];
                    yv3 += h[n + 3] * sBC[j][16 + n + 3];
                }
            } else {
#pragma unroll
                for (int n = 0; n < 16; n += 4) {
                    const float w0 = __expf(dt * Ar[n]);
                    const float w1 = __expf(dt * Ar[n + 1]);
                    const float w2 = __expf(dt * Ar[n + 2]);
                    const float w3 = __expf(dt * Ar[n + 3]);
                    h[n]     = w0 * h[n]     + sBC[j][n]     * du;
                    h[n + 1] = w1 * h[n + 1] + sBC[j][n + 1] * du;
                    h[n + 2] = w2 * h[n + 2] + sBC[j][n + 2] * du;
                    h[n + 3] = w3 * h[n + 3] + sBC[j][n + 3] * du;
                    yv0 += h[n]     * sBC[j][16 + n];
                    yv1 += h[n + 1] * sBC[j][16 + n + 1];
                    yv2 += h[n + 2] * sBC[j][16 + n + 2];
                    yv3 += h[n + 3] * sBC[j][16 + n + 3];
                }
            }
            const float yv = (yv0 + yv1) + (yv2 + yv3);
            const float vout = (yv + ut * Dd) * silu_f(cr[j]);
            __half hh, ll; split_hl_h(vout, hh, ll);
            const size_t ix = (rowbase + tt + j) * DINNER + d;
            yh[ix] = hh; yl[ix] = ll;
        }
        __syncthreads();
    }
}

// ---------------- launch ----------------
extern "C" void kernel_launch(void* const* d_in, const int* in_sizes, int n_in,
                              void* d_out, int out_size)
{
    const float* x     = (const float*)d_in[0];
    const float* W_in  = (const float*)d_in[1];
    const float* convw = (const float*)d_in[2];
    const float* convb = (const float*)d_in[3];
    const float* W_x   = (const float*)d_in[4];
    const float* W_dt  = (const float*)d_in[5];
    const float* b_dt  = (const float*)d_in[6];
    const float* A_log = (const float*)d_in[7];
    const float* Dv    = (const float*)d_in[8];
    const float* W_out = (const float*)d_in[9];
    float* out = (float*)d_out;

    float *xz, *u, *xdbl, *delta, *part;
    __half *xh16, *xl16, *wih16, *woh16, *yh16, *yl16;
    __nv_bfloat16 *wdh, *wdl, *wxh, *wxl, *uh, *ul, *dth, *dtl;
    cudaGetSymbolAddress((void**)&xz,    g_xz);
    cudaGetSymbolAddress((void**)&u,     g_u);
    cudaGetSymbolAddress((void**)&xdbl,  g_xdbl);
    cudaGetSymbolAddress((void**)&delta, g_delta);
    cudaGetSymbolAddress((void**)&part,  g_part);
    cudaGetSymbolAddress((void**)&xh16,  g_xh16);  cudaGetSymbolAddress((void**)&xl16, g_xl16);
    cudaGetSymbolAddress((void**)&wih16, g_wih16);
    cudaGetSymbolAddress((void**)&woh16, g_woh16);
    cudaGetSymbolAddress((void**)&yh16,  g_yh16);  cudaGetSymbolAddress((void**)&yl16, g_yl16);
    cudaGetSymbolAddress((void**)&wdh, g_wdh); cudaGetSymbolAddress((void**)&wdl, g_wdl);
    cudaGetSymbolAddress((void**)&wxh, g_wxh); cudaGetSymbolAddress((void**)&wxl, g_wxl);
    cudaGetSymbolAddress((void**)&uh,  g_uh);  cudaGetSymbolAddress((void**)&ul,  g_ul);
    cudaGetSymbolAddress((void**)&dth, g_dth); cudaGetSymbolAddress((void**)&dtl, g_dtl);

    constexpr int SMEM128 = 2 * (2 * 128 * A_STRIDE + 2 * B_MAT_SZ) * 2;  // 75776 B
    constexpr int SMEM64  = 2 * (2 * 64  * A_STRIDE + 2 * B_MAT_SZ) * 2;  // 55296 B
    constexpr int SMEMF16 = 2 * (2 * 128 * A_STRIDE + B_MAT_SZ) * 2;      // 58368 B
    cudaFuncSetAttribute(gemm_bf16x3_k<128>, cudaFuncAttributeMaxDynamicSharedMemorySize, SMEM128);
    cudaFuncSetAttribute(gemm3_splitk_k,     cudaFuncAttributeMaxDynamicSharedMemorySize, SMEM64);
    cudaFuncSetAttribute(gemm_f16x2_k,       cudaFuncAttributeMaxDynamicSharedMemorySize, SMEMF16);

    // 1,2,3: conversions needed by GEMM1/GEMM3
    cvt_hilo_h_k<<<(BL * DMODEL / 4 + 255) / 256, 256>>>(x, xh16, xl16, BL * DMODEL / 4);
    cvt_h_k<<<(DMODEL * 2 * DINNER / 4 + 255) / 256, 256>>>(W_in, wih16, DMODEL * 2 * DINNER / 4);
    cvt_pad_wx_k<<<(DINNER * XDW) / 256, 256>>>(W_x, wxh, wxl);

    // 4: xz = x @ W_in   fp16 2-MMA  [4096,1024]@[1024,4096]
    gemm_f16x2_k<<<dim3((2 * DINNER) / 128, BL / 128), 256, SMEMF16>>>(
        xh16, xl16, wih16, xz, BL, 2 * DINNER, DMODEL, DMODEL);

    // 5: u = silu(causal_dwconv(xs) + b)  (+ bf16 hi/lo)
    conv_silu_kernel<<<(BL * DINNER / 4) / 256, 256>>>(xz, convw, convb, u, uh, ul);

    // 6: x_dbl = u @ W_x (padded N=128), split-K x4 -> partials (bf16 3-MMA)
    gemm3_splitk_k<<<dim3(KSPLIT, BL / 64), 256, SMEM64>>>(uh, ul, wxh, wxl, part);

    // 7: reduce partials -> xdbl fp32 + dt bf16 hi/lo
    reduce_xdbl_k<<<(BL * XDW) / 256, 256>>>(xdbl, dth, dtl);

    // 8: W_dt conversion (bf16)
    cvt_hilo_k<<<(DTRANK * DINNER / 4 + 255) / 256, 256>>>(W_dt, wdh, wdl, DTRANK * DINNER / 4);

    // 9: delta = softplus(dt @ W_dt + b_dt)  bf16 3-MMA  [4096,64(str128)]@[64,2048]
    gemm_bf16x3_k<128><<<dim3(DINNER / 128, BL / 128), 256, SMEM128>>>(
        dth, dtl, wdh, wdl, delta, BL, DINNER, DTRANK, XDW, b_dt, 1, nullptr, nullptr);

    // 10-12: chunked selective scan (emits y as fp16 hi/lo)
    scanA_k<<<dim3(BL / 128, NCHK), 128>>>(delta, xdbl, u, A_log);
    scanB_k<<<BL / 128, 128>>>(A_log);
    scanC_k<<<dim3(BL / 128, NCHK), 128>>>(delta, xdbl, u, A_log, Dv, xz, yh16, yl16);

    // 13: W_out conversion (fp16)
    cvt_h_k<<<(DINNER * DMODEL / 4 + 255) / 256, 256>>>(W_out, woh16, DINNER * DMODEL / 4);

    // 14: out = y @ W_out   fp16 2-MMA  [4096,2048]@[2048,1024]
    gemm_f16x2_k<<<dim3(DMODEL / 128, BL / 128), 256, SMEMF16>>>(
        yh16, yl16, woh16, out, BL, DMODEL, DINNER, DINNER);
}

// round 17
// speedup vs baseline: 1.2235x; 1.0469x over previous
#include <cuda_runtime.h>
#include <cuda_bf16.h>
#include <cuda_fp16.h>
#include <math.h>
#include <stdint.h>

// Problem constants
#define B_SZ   2
#define LSEQ   2048
#define DMODEL 1024
#define DINNER 2048
#define DSTATE 16
#define DCONV  4
#define DTRANK 64
#define BL     (B_SZ * LSEQ)          // 4096 rows
#define XDW    128                    // padded x_dbl width (dt 0..63, B 64..79, C 80..95)
#define NCHK   16
#define TCH    (LSEQ / NCHK)          // 128
#define KSPLIT 4

// ---------------- scratch ----------------
__device__ float g_xz[(size_t)BL * (2 * DINNER)];
__device__ float g_u[(size_t)BL * DINNER];
__device__ float g_xdbl[(size_t)BL * XDW];
__device__ float g_delta[(size_t)BL * DINNER];
__device__ float g_part[(size_t)KSPLIT * BL * XDW];    // split-K partials for GEMM3
__device__ float g_hloc[(size_t)NCHK * DSTATE * BL];   // [chunk][n][ch]
__device__ float g_h0[(size_t)NCHK * DSTATE * BL];
__device__ float g_sumdt[(size_t)NCHK * BL];

// fp16 operands for the big 2-MMA GEMMs (1 and 6)
__device__ __half g_xh16[(size_t)BL * DMODEL], g_xl16[(size_t)BL * DMODEL];
__device__ __half g_wih16[(size_t)DMODEL * 2 * DINNER];
__device__ __half g_woh16[(size_t)DINNER * DMODEL];
__device__ __half g_yh16[(size_t)BL * DINNER], g_yl16[(size_t)BL * DINNER];

// bf16 operands for the small 3-MMA GEMMs (3 and 4) — proven path, untouched
__device__ __nv_bfloat16 g_wdh[(size_t)DTRANK * DINNER], g_wdl[(size_t)DTRANK * DINNER];
__device__ __nv_bfloat16 g_wxh[(size_t)DINNER * XDW],    g_wxl[(size_t)DINNER * XDW];
__device__ __nv_bfloat16 g_uh[(size_t)BL * DINNER],  g_ul[(size_t)BL * DINNER];
__device__ __nv_bfloat16 g_dth[(size_t)BL * XDW],    g_dtl[(size_t)BL * XDW];

// ---------------- helpers ----------------
__device__ __forceinline__ float softplus_f(float x) {
    return (x > 20.f) ? x : log1pf(expf(x));
}
__device__ __forceinline__ float silu_f(float x) {
    return x * (1.f / (1.f + __expf(-x)));
}
__device__ __forceinline__ void split_hl(float v, __nv_bfloat16& h, __nv_bfloat16& l) {
    h = __float2bfloat16_rn(v);
    l = __float2bfloat16_rn(v - __bfloat162float(h));
}
__device__ __forceinline__ void split_hl_h(float v, __half& h, __half& l) {
    h = __float2half_rn(v);
    l = __float2half_rn(v - __half2float(h));
}

// fp32 -> (hi, lo) fp16, 4 elems/thread
__global__ void cvt_hilo_h_k(const float* __restrict__ s, __half* __restrict__ h,
                             __half* __restrict__ l, int n4)
{
    int i = blockIdx.x * blockDim.x + threadIdx.x;
    if (i >= n4) return;
    float4 v = ((const float4*)s)[i];
    __half h0, h1, h2, h3, l0, l1, l2, l3;
    split_hl_h(v.x, h0, l0); split_hl_h(v.y, h1, l1);
    split_hl_h(v.z, h2, l2); split_hl_h(v.w, h3, l3);
    ((__half2*)h)[i * 2]     = __half2(h0, h1);
    ((__half2*)h)[i * 2 + 1] = __half2(h2, h3);
    ((__half2*)l)[i * 2]     = __half2(l0, l1);
    ((__half2*)l)[i * 2 + 1] = __half2(l2, l3);
}

// fp32 -> fp16 (round-to-nearest), 4 elems/thread
__global__ void cvt_h_k(const float* __restrict__ s, __half* __restrict__ h, int n4)
{
    int i = blockIdx.x * blockDim.x + threadIdx.x;
    if (i >= n4) return;
    float4 v = ((const float4*)s)[i];
    ((__half2*)h)[i * 2]     = __floats2half2_rn(v.x, v.y);
    ((__half2*)h)[i * 2 + 1] = __floats2half2_rn(v.z, v.w);
}

// fp32 -> (hi, lo) bf16, 4 elems/thread (W_dt)
__global__ void cvt_hilo_k(const float* __restrict__ s, __nv_bfloat16* __restrict__ h,
                           __nv_bfloat16* __restrict__ l, int n4)
{
    int i = blockIdx.x * blockDim.x + threadIdx.x;
    if (i >= n4) return;
    float4 v = ((const float4*)s)[i];
    __nv_bfloat16 h0, h1, h2, h3, l0, l1, l2, l3;
    split_hl(v.x, h0, l0); split_hl(v.y, h1, l1);
    split_hl(v.z, h2, l2); split_hl(v.w, h3, l3);
    ((__nv_bfloat162*)h)[i * 2]     = __nv_bfloat162(h0, h1);
    ((__nv_bfloat162*)h)[i * 2 + 1] = __nv_bfloat162(h2, h3);
    ((__nv_bfloat162*)l)[i * 2]     = __nv_bfloat162(l0, l1);
    ((__nv_bfloat162*)l)[i * 2 + 1] = __nv_bfloat162(l2, l3);
}

// W_x [2048,96] -> padded hi/lo [2048,128] (cols >=96 zero)
__global__ void cvt_pad_wx_k(const float* __restrict__ s, __nv_bfloat16* __restrict__ h,
                             __nv_bfloat16* __restrict__ l)
{
    int i = blockIdx.x * blockDim.x + threadIdx.x;   // over 2048*128
    int col = i & (XDW - 1), k = i >> 7;
    float v = (col < 96) ? s[k * 96 + col] : 0.f;
    __nv_bfloat16 hh, ll; split_hl(v, hh, ll);
    h[i] = hh; l[i] = ll;
}

// split-K reduction for GEMM3: xdbl = sum parts, also dt hi/lo (bf16)
__global__ void reduce_xdbl_k(float* __restrict__ xdbl,
                              __nv_bfloat16* __restrict__ dth, __nv_bfloat16* __restrict__ dtl)
{
    const int i = blockIdx.x * blockDim.x + threadIdx.x;   // over BL*XDW
    float v = g_part[i];
#pragma unroll
    for (int p = 1; p < KSPLIT; ++p) v += g_part[(size_t)p * BL * XDW + i];
    xdbl[i] = v;
    __nv_bfloat16 hh, ll; split_hl(v, hh, ll);
    dth[i] = hh; dtl[i] = ll;
}

// ---------------- shared GEMM plumbing ----------------
#define CP16(dst, src) \
    asm volatile("cp.async.cg.shared.global [%0], [%1], 16;" :: "r"(dst), "l"(src))
#define CP_COMMIT() asm volatile("cp.async.commit_group;" ::: "memory")
#define LDSM4(r, addr) \
    asm volatile("ldmatrix.sync.aligned.m8n8.x4.shared.b16 {%0,%1,%2,%3}, [%4];" \
        : "=r"((r)[0]), "=r"((r)[1]), "=r"((r)[2]), "=r"((r)[3]) : "r"(addr))
#define LDSM4T(r, addr) \
    asm volatile("ldmatrix.sync.aligned.m8n8.x4.trans.shared.b16 {%0,%1,%2,%3}, [%4];" \
        : "=r"((r)[0]), "=r"((r)[1]), "=r"((r)[2]), "=r"((r)[3]) : "r"(addr))
#define MMA16816(d, a, b0r, b1r) \
    asm volatile("mma.sync.aligned.m16n8k16.row.col.f32.bf16.bf16.f32 " \
        "{%0,%1,%2,%3}, {%4,%5,%6,%7}, {%8,%9}, {%0,%1,%2,%3};" \
        : "+f"((d)[0]), "+f"((d)[1]), "+f"((d)[2]), "+f"((d)[3]) \
        : "r"((a)[0]), "r"((a)[1]), "r"((a)[2]), "r"((a)[3]), "r"(b0r), "r"(b1r))
#define MMAH16816(d, a, b0r, b1r) \
    asm volatile("mma.sync.aligned.m16n8k16.row.col.f32.f16.f16.f32 " \
        "{%0,%1,%2,%3}, {%4,%5,%6,%7}, {%8,%9}, {%0,%1,%2,%3};" \
        : "+f"((d)[0]), "+f"((d)[1]), "+f"((d)[2]), "+f"((d)[3]) \
        : "r"((a)[0]), "r"((a)[1]), "r"((a)[2]), "r"((a)[3]), "r"(b0r), "r"(b1r))

#define A_STRIDE 40      // 16-bit units; 80 B rows -> conflict-free LDSM (bf16 kernels)
#define B_STRIDE 136     // 272 B rows -> conflict-free LDSM.trans
#define B_MAT_SZ (32 * B_STRIDE)

// ---------------- fp16 2-MMA GEMM (GEMM1 / GEMM6), BK=64 ----------------
// C[M,N] fp32 = (Ah+Al)[M,K](astr) @ B[K,N], A split exact in fp16, B single fp16.
// BK=64: half the iterations/barriers of BK=32; 4 independent k-steps per phase.
#define AF_STRIDE 72                      // 64+8 halfs; 144 B rows, conflict-free LDSM
#define BF_MAT    (64 * B_STRIDE)         // 8704 halfs

__global__ __launch_bounds__(256, 2)
void gemm_f16x2_k(const __half* __restrict__ Ah, const __half* __restrict__ Al,
                  const __half* __restrict__ Bh, float* __restrict__ C,
                  int M, int N, int K, int astr)
{
    constexpr int BM    = 128;
    constexpr int MT    = 4;
    constexpr int WM    = 64;
    constexpr int A_MAT = BM * AF_STRIDE;               // 9216 halfs
    constexpr int STAGE = 2 * A_MAT + BF_MAT;           // 27136 halfs = 54272 B

    extern __shared__ __align__(16) __half smh[];
    const uint32_t smbase = (uint32_t)__cvta_generic_to_shared(smh);

    const int tid  = threadIdx.x;
    const int lane = tid & 31;
    const int w    = tid >> 5;
    const int wm   = w >> 2;
    const int wn   = w & 3;
    const int bm   = blockIdx.y * BM;
    const int bn   = blockIdx.x * 128;

    const __half* Asrc[2] = {Ah, Al};

    auto fill = [&](int stg, int k0) {
        const uint32_t stgA = smbase + (uint32_t)(stg * STAGE) * 2;
        const uint32_t stgB = stgA + (uint32_t)(2 * A_MAT) * 2;
        // A: 128 rows x 64 halfs = 1024 cp16; 4 per thread per matrix
#pragma unroll
        for (int mat = 0; mat < 2; ++mat) {
#pragma unroll
            for (int i = 0; i < 4; ++i) {
                int c = tid + i * 256;
                int r = c >> 3, kc = (c & 7) << 3;
                uint32_t dst = stgA + (uint32_t)(mat * A_MAT + r * AF_STRIDE + kc) * 2;
                CP16(dst, Asrc[mat] + (size_t)(bm + r) * astr + k0 + kc);
            }
        }
        // B: 64 rows x 128 halfs = 1024 cp16; 4 per thread
#pragma unroll
        for (int i = 0; i < 4; ++i) {
            int c = tid + i * 256;
            int r = c >> 4, nc = (c & 15) << 3;
            uint32_t dst = stgB + (uint32_t)(r * B_STRIDE + nc) * 2;
            CP16(dst, Bh + (size_t)(k0 + r) * N + bn + nc);
        }
    };

    float acc[MT][4][4];
#pragma unroll
    for (int i = 0; i < MT; ++i)
#pragma unroll
        for (int j = 0; j < 4; ++j)
#pragma unroll
            for (int q = 0; q < 4; ++q) acc[i][j][q] = 0.f;

    const uint32_t aByte = (uint32_t)((wm * WM + (lane & 15)) * AF_STRIDE + ((lane >> 4) << 3)) * 2;
    const uint32_t bByte = (uint32_t)((lane & 15) * B_STRIDE + wn * 32 + ((lane >> 4) << 3)) * 2;

    const int KT = K >> 6;                 // K / 64
    fill(0, 0);
    CP_COMMIT();

    for (int it = 0; it < KT; ++it) {
        const int cur = it & 1;
        if (it + 1 < KT) { fill(cur ^ 1, (it + 1) << 6); CP_COMMIT(); }
        if (it + 1 < KT) asm volatile("cp.async.wait_group 1;" ::: "memory");
        else             asm volatile("cp.async.wait_group 0;" ::: "memory");
        __syncthreads();

        const uint32_t stgA = smbase + (uint32_t)(cur * STAGE) * 2;
        const uint32_t stgB = stgA + (uint32_t)(2 * A_MAT) * 2;

#pragma unroll
        for (int ks = 0; ks < 64; ks += 16) {
            uint32_t bhf[2][4];
#pragma unroll
            for (int p = 0; p < 2; ++p) {
                uint32_t off = bByte + (uint32_t)(ks * B_STRIDE + p * 16) * 2;
                LDSM4T(bhf[p], stgB + off);
            }
#pragma unroll
            for (int mt = 0; mt < MT; ++mt) {
                uint32_t ahf[4], alf[4];
                uint32_t off = aByte + (uint32_t)(mt * 16 * AF_STRIDE + ks) * 2;
                LDSM4(ahf, stgA + off);
                LDSM4(alf, stgA + (uint32_t)(A_MAT * 2) + off);
#pragma unroll
                for (int nt = 0; nt < 4; ++nt) {
                    const int p = nt >> 1, q = (nt & 1) << 1;
                    MMAH16816(acc[mt][nt], ahf, bhf[p][q], bhf[p][q + 1]); // hi*B
                    MMAH16816(acc[mt][nt], alf, bhf[p][q], bhf[p][q + 1]); // lo*B
                }
            }
        }
        __syncthreads();
    }

#pragma unroll
    for (int mt = 0; mt < MT; ++mt) {
        const int r0 = bm + wm * WM + mt * 16 + (lane >> 2);
#pragma unroll
        for (int nt = 0; nt < 4; ++nt) {
            const int c0 = bn + wn * 32 + nt * 8 + ((lane & 3) << 1);
            *(float2*)(C + (size_t)r0 * N + c0)       = make_float2(acc[mt][nt][0], acc[mt][nt][1]);
            *(float2*)(C + (size_t)(r0 + 8) * N + c0) = make_float2(acc[mt][nt][2], acc[mt][nt][3]);
        }
    }
}

// ---------------- bf16 3-MMA GEMM (GEMM4) — R8-exact hot kernel ----------------
template<int BM>
__global__ __launch_bounds__(256, 2)
void gemm_bf16x3_k(const __nv_bfloat16* __restrict__ Ah, const __nv_bfloat16* __restrict__ Al,
                   const __nv_bfloat16* __restrict__ Bh, const __nv_bfloat16* __restrict__ Bl,
                   float* __restrict__ C, int M, int N, int K, int astr,
                   const float* __restrict__ bias, int mode,
                   __nv_bfloat16* __restrict__ Ch, __nv_bfloat16* __restrict__ Cl)
{
    constexpr int MT      = BM / 32;
    constexpr int WM      = BM / 2;
    constexpr int A_MAT   = BM * A_STRIDE;
    constexpr int STAGE   = 2 * A_MAT + 2 * B_MAT_SZ;

    extern __shared__ __align__(16) __nv_bfloat16 sm[];
    const uint32_t smbase = (uint32_t)__cvta_generic_to_shared(sm);

    const int tid  = threadIdx.x;
    const int lane = tid & 31;
    const int w    = tid >> 5;
    const int wm   = w >> 2;
    const int wn   = w & 3;
    const int bm   = blockIdx.y * BM;
    const int bn   = blockIdx.x * 128;

    const __nv_bfloat16* Asrc[2] = {Ah, Al};
    const __nv_bfloat16* Bsrc[2] = {Bh, Bl};

    auto fill = [&](int stg, int k0) {
        const uint32_t stgA = smbase + (uint32_t)(stg * STAGE) * 2;
        const uint32_t stgB = stgA + (uint32_t)(2 * A_MAT) * 2;
#pragma unroll
        for (int mat = 0; mat < 2; ++mat) {
#pragma unroll
            for (int i = 0; i < BM * 4 / 256; ++i) {
                int c = tid + i * 256;
                int r = c >> 2, kc = (c & 3) << 3;
                uint32_t dst = stgA + (uint32_t)(mat * A_MAT + r * A_STRIDE + kc) * 2;
                CP16(dst, Asrc[mat] + (size_t)(bm + r) * astr + k0 + kc);
            }
        }
#pragma unroll
        for (int mat = 0; mat < 2; ++mat) {
#pragma unroll
            for (int i = 0; i < 2; ++i) {
                int c = tid + i * 256;
                int r = c >> 4, nc = (c & 15) << 3;
                uint32_t dst = stgB + (uint32_t)(mat * B_MAT_SZ + r * B_STRIDE + nc) * 2;
                CP16(dst, Bsrc[mat] + (size_t)(k0 + r) * N + bn + nc);
            }
        }
    };

    float acc[MT][4][4];
#pragma unroll
    for (int i = 0; i < MT; ++i)
#pragma unroll
        for (int j = 0; j < 4; ++j)
#pragma unroll
            for (int q = 0; q < 4; ++q) acc[i][j][q] = 0.f;

    const uint32_t aByte = (uint32_t)((wm * WM + (lane & 15)) * A_STRIDE + ((lane >> 4) << 3)) * 2;
    const uint32_t bByte = (uint32_t)((lane & 15) * B_STRIDE + wn * 32 + ((lane >> 4) << 3)) * 2;

    const int KT = K >> 5;
    fill(0, 0);
    CP_COMMIT();

    for (int it = 0; it < KT; ++it) {
        const int cur = it & 1;
        if (it + 1 < KT) { fill(cur ^ 1, (it + 1) << 5); CP_COMMIT(); }
        if (it + 1 < KT) asm volatile("cp.async.wait_group 1;" ::: "memory");
        else             asm volatile("cp.async.wait_group 0;" ::: "memory");
        __syncthreads();

        const uint32_t stgA = smbase + (uint32_t)(cur * STAGE) * 2;
        const uint32_t stgB = stgA + (uint32_t)(2 * A_MAT) * 2;

#pragma unroll
        for (int ks = 0; ks < 32; ks += 16) {
            uint32_t bhf[2][4], blf[2][4];
#pragma unroll
            for (int p = 0; p < 2; ++p) {
                uint32_t off = bByte + (uint32_t)(ks * B_STRIDE + p * 16) * 2;
                LDSM4T(bhf[p], stgB + off);
                LDSM4T(blf[p], stgB + (uint32_t)(B_MAT_SZ * 2) + off);
            }
#pragma unroll
            for (int mt = 0; mt < MT; ++mt) {
                uint32_t ahf[4], alf[4];
                uint32_t off = aByte + (uint32_t)(mt * 16 * A_STRIDE + ks) * 2;
                LDSM4(ahf, stgA + off);
                LDSM4(alf, stgA + (uint32_t)(A_MAT * 2) + off);
#pragma unroll
                for (int nt = 0; nt < 4; ++nt) {
                    const int p = nt >> 1, q = (nt & 1) << 1;
                    MMA16816(acc[mt][nt], ahf, bhf[p][q], bhf[p][q + 1]); // hi*hi
                    MMA16816(acc[mt][nt], ahf, blf[p][q], blf[p][q + 1]); // hi*lo
                    MMA16816(acc[mt][nt], alf, bhf[p][q], bhf[p][q + 1]); // lo*hi
                }
            }
        }
        __syncthreads();
    }

#pragma unroll
    for (int mt = 0; mt < MT; ++mt) {
        const int r0 = bm + wm * WM + mt * 16 + (lane >> 2);
#pragma unroll
        for (int nt = 0; nt < 4; ++nt) {
            const int c0 = bn + wn * 32 + nt * 8 + ((lane & 3) << 1);
            float v0 = acc[mt][nt][0], v1 = acc[mt][nt][1];
            float v2 = acc[mt][nt][2], v3 = acc[mt][nt][3];
            if (mode == 1) {
                const float b0 = bias[c0], b1 = bias[c0 + 1];
                v0 = softplus_f(v0 + b0); v1 = softplus_f(v1 + b1);
                v2 = softplus_f(v2 + b0); v3 = softplus_f(v3 + b1);
            }
            *(float2*)(C + (size_t)r0 * N + c0)       = make_float2(v0, v1);
            *(float2*)(C + (size_t)(r0 + 8) * N + c0) = make_float2(v2, v3);
            if (mode == 2) {
                __nv_bfloat16 h0, l0, h1, l1, h2, l2, h3, l3;
                split_hl(v0, h0, l0); split_hl(v1, h1, l1);
                split_hl(v2, h2, l2); split_hl(v3, h3, l3);
                *(__nv_bfloat162*)(Ch + (size_t)r0 * N + c0)       = __nv_bfloat162(h0, h1);
                *(__nv_bfloat162*)(Cl + (size_t)r0 * N + c0)       = __nv_bfloat162(l0, l1);
                *(__nv_bfloat162*)(Ch + (size_t)(r0 + 8) * N + c0) = __nv_bfloat162(h2, h3);
                *(__nv_bfloat162*)(Cl + (size_t)(r0 + 8) * N + c0) = __nv_bfloat162(l2, l3);
            }
        }
    }
}

// ---------------- dedicated split-K GEMM3 kernel (bf16, compile-time shapes) ----------------
__global__ __launch_bounds__(256, 2)
void gemm3_splitk_k(const __nv_bfloat16* __restrict__ Ah, const __nv_bfloat16* __restrict__ Al,
                    const __nv_bfloat16* __restrict__ Bh, const __nv_bfloat16* __restrict__ Bl,
                    float* __restrict__ Cbase)
{
    constexpr int BM   = 64;
    constexpr int MT   = 2;
    constexpr int WM   = 32;
    constexpr int A_MAT = BM * A_STRIDE;
    constexpr int STAGE = 2 * A_MAT + 2 * B_MAT_SZ;
    constexpr int N    = XDW;
    constexpr int KSEG = DINNER / KSPLIT;   // 512
    constexpr int KT   = KSEG / 32;         // 16

    extern __shared__ __align__(16) __nv_bfloat16 sm[];
    const uint32_t smbase = (uint32_t)__cvta_generic_to_shared(sm);

    const int tid  = threadIdx.x;
    const int lane = tid & 31;
    const int w    = tid >> 5;
    const int wm   = w >> 2;
    const int wn   = w & 3;
    const int bm   = blockIdx.y * BM;
    const int kbase = blockIdx.x * KSEG;
    float* __restrict__ C = Cbase + (size_t)blockIdx.x * BL * XDW;

    const __nv_bfloat16* Asrc[2] = {Ah, Al};
    const __nv_bfloat16* Bsrc[2] = {Bh, Bl};

    auto fill = [&](int stg, int k0) {
        const uint32_t stgA = smbase + (uint32_t)(stg * STAGE) * 2;
        const uint32_t stgB = stgA + (uint32_t)(2 * A_MAT) * 2;
#pragma unroll
        for (int mat = 0; mat < 2; ++mat) {
            int c = tid;
            int r = c >> 2, kc = (c & 3) << 3;
            uint32_t dst = stgA + (uint32_t)(mat * A_MAT + r * A_STRIDE + kc) * 2;
            CP16(dst, Asrc[mat] + (size_t)(bm + r) * DINNER + k0 + kc);
        }
#pragma unroll
        for (int mat = 0; mat < 2; ++mat) {
#pragma unroll
            for (int i = 0; i < 2; ++i) {
                int c = tid + i * 256;
                int r = c >> 4, nc = (c & 15) << 3;
                uint32_t dst = stgB + (uint32_t)(mat * B_MAT_SZ + r * B_STRIDE + nc) * 2;
                CP16(dst, Bsrc[mat] + (size_t)(k0 + r) * N + nc);
            }
        }
    };

    float acc[MT][4][4];
#pragma unroll
    for (int i = 0; i < MT; ++i)
#pragma unroll
        for (int j = 0; j < 4; ++j)
#pragma unroll
            for (int q = 0; q < 4; ++q) acc[i][j][q] = 0.f;

    const uint32_t aByte = (uint32_t)((wm * WM + (lane & 15)) * A_STRIDE + ((lane >> 4) << 3)) * 2;
    const uint32_t bByte = (uint32_t)((lane & 15) * B_STRIDE + wn * 32 + ((lane >> 4) << 3)) * 2;

    fill(0, kbase);
    CP_COMMIT();

    for (int it = 0; it < KT; ++it) {
        const int cur = it & 1;
        if (it + 1 < KT) { fill(cur ^ 1, kbase + ((it + 1) << 5)); CP_COMMIT(); }
        if (it + 1 < KT) asm volatile("cp.async.wait_group 1;" ::: "memory");
        else             asm volatile("cp.async.wait_group 0;" ::: "memory");
        __syncthreads();

        const uint32_t stgA = smbase + (uint32_t)(cur * STAGE) * 2;
        const uint32_t stgB = stgA + (uint32_t)(2 * A_MAT) * 2;

#pragma unroll
        for (int ks = 0; ks < 32; ks += 16) {
            uint32_t bhf[2][4], blf[2][4];
#pragma unroll
            for (int p = 0; p < 2; ++p) {
                uint32_t off = bByte + (uint32_t)(ks * B_STRIDE + p * 16) * 2;
                LDSM4T(bhf[p], stgB + off);
                LDSM4T(blf[p], stgB + (uint32_t)(B_MAT_SZ * 2) + off);
            }
#pragma unroll
            for (int mt = 0; mt < MT; ++mt) {
                uint32_t ahf[4], alf[4];
                uint32_t off = aByte + (uint32_t)(mt * 16 * A_STRIDE + ks) * 2;
                LDSM4(ahf, stgA + off);
                LDSM4(alf, stgA + (uint32_t)(A_MAT * 2) + off);
#pragma unroll
                for (int nt = 0; nt < 4; ++nt) {
                    const int p = nt >> 1, q = (nt & 1) << 1;
                    MMA16816(acc[mt][nt], ahf, bhf[p][q], bhf[p][q + 1]);
                    MMA16816(acc[mt][nt], ahf, blf[p][q], blf[p][q + 1]);
                    MMA16816(acc[mt][nt], alf, bhf[p][q], bhf[p][q + 1]);
                }
            }
        }
        __syncthreads();
    }

#pragma unroll
    for (int mt = 0; mt < MT; ++mt) {
        const int r0 = bm + wm * WM + mt * 16 + (lane >> 2);
#pragma unroll
        for (int nt = 0; nt < 4; ++nt) {
            const int c0 = wn * 32 + nt * 8 + ((lane & 3) << 1);
            *(float2*)(C + (size_t)r0 * N + c0) =
                make_float2(acc[mt][nt][0], acc[mt][nt][1]);
            *(float2*)(C + (size_t)(r0 + 8) * N + c0) =
                make_float2(acc[mt][nt][2], acc[mt][nt][3]);
        }
    }
}

// ---------------- causal depthwise conv (width 4) + SiLU, x4 vectorized ----------------
__global__ void conv_silu_kernel(const float* __restrict__ xz, const float* __restrict__ cw,
                                 const float* __restrict__ cb, float* __restrict__ u,
                                 __nv_bfloat16* __restrict__ uh, __nv_bfloat16* __restrict__ ul)
{
    const int i4 = blockIdx.x * blockDim.x + threadIdx.x;   // over BL*DINNER/4
    const int d4 = (i4 << 2) & (DINNER - 1);
    const int bl = i4 >> 9;                                 // DINNER/4 = 512
    const int l  = bl & (LSEQ - 1);

    float4 s = *(const float4*)(cb + d4);
    const float4 w0 = *(const float4*)(cw + (d4 + 0) * 4);
    const float4 w1 = *(const float4*)(cw + (d4 + 1) * 4);
    const float4 w2 = *(const float4*)(cw + (d4 + 2) * 4);
    const float4 w3 = *(const float4*)(cw + (d4 + 3) * 4);

    const float* base = xz + (size_t)(bl - l) * (2 * DINNER) + d4;
#pragma unroll
    for (int k = 0; k < 4; ++k) {
        const int ls = l - 3 + k;
        if (ls >= 0) {
            const float4 xv = *(const float4*)(base + (size_t)ls * (2 * DINNER));
            s.x += xv.x * (&w0.x)[k];
            s.y += xv.y * (&w1.x)[k];
            s.z += xv.z * (&w2.x)[k];
            s.w += xv.w * (&w3.x)[k];
        }
    }
    const float u0 = silu_f(s.x), u1 = silu_f(s.y), u2 = silu_f(s.z), u3 = silu_f(s.w);
    const size_t idx = (size_t)bl * DINNER + d4;
    *(float4*)(u + idx) = make_float4(u0, u1, u2, u3);

    __nv_bfloat16 h0, l0, h1, l1, h2, l2, h3, l3;
    split_hl(u0, h0, l0); split_hl(u1, h1, l1);
    split_hl(u2, h2, l2); split_hl(u3, h3, l3);
    ((__nv_bfloat162*)(uh + idx))[0] = __nv_bfloat162(h0, h1);
    ((__nv_bfloat162*)(uh + idx))[1] = __nv_bfloat162(h2, h3);
    ((__nv_bfloat162*)(ul + idx))[0] = __nv_bfloat162(l0, l1);
    ((__nv_bfloat162*)(ul + idx))[1] = __nv_bfloat162(l2, l3);
}

// ---------------- chunked selective scan ----------------
__global__ __launch_bounds__(128)
void scanA_k(const float* __restrict__ delta, const float* __restrict__ xdbl,
             const float* __restrict__ u, const float* __restrict__ A_log)
{
    __shared__ float sBC[4][32];
    const int tid = threadIdx.x;
    const int ch  = blockIdx.x * 128 + tid;
    const int b   = ch >> 11;
    const int d   = ch & (DINNER - 1);
    const int chunk = blockIdx.y;

    float Ar[16];
#pragma unroll
    for (int n = 0; n < 16; ++n) Ar[n] = -expf(A_log[d * DSTATE + n]);
    const float A0 = Ar[0];
    bool structured = true;
#pragma unroll
    for (int n = 1; n < 16; ++n)
        if (fabsf(Ar[n] - A0 * (float)(n + 1)) > 1e-4f * fabsf(Ar[n])) structured = false;

    float h[16];
#pragma unroll
    for (int n = 0; n < 16; ++n) h[n] = 0.f;
    float sumdt = 0.f;

    const size_t rowbase = (size_t)b * LSEQ + chunk * TCH;
    const int sj = tid >> 5, sc = tid & 31;

    for (int tt = 0; tt < TCH; tt += 4) {
        sBC[sj][sc] = xdbl[(rowbase + tt + sj) * XDW + DTRANK + sc];
        float cd[4], cu[4];
#pragma unroll
        for (int j = 0; j < 4; ++j) {
            const size_t ix = (rowbase + tt + j) * DINNER + d;
            cd[j] = delta[ix]; cu[j] = u[ix];
        }
        __syncthreads();
#pragma unroll
        for (int j = 0; j < 4; ++j) {
            const float dt = cd[j], du = dt * cu[j];
            sumdt += dt;
            if (structured) {
                const float p = __expf(dt * A0);
                float wv[16];
                wv[0] = p;
#pragma unroll
                for (int n = 1; n < 16; ++n) wv[n] = wv[(n - 1) >> 1] * wv[n >> 1];
#pragma unroll
                for (int n = 0; n < 16; ++n) h[n] = wv[n] * h[n] + sBC[j][n] * du;
            } else {
#pragma unroll
                for (int n = 0; n < 16; ++n)
                    h[n] = __expf(dt * Ar[n]) * h[n] + sBC[j][n] * du;
            }
        }
        __syncthreads();
    }
    g_sumdt[(size_t)chunk * BL + ch] = sumdt;
#pragma unroll
    for (int n = 0; n < 16; ++n)
        g_hloc[((size_t)chunk * DSTATE + n) * BL + ch] = h[n];
}

__global__ __launch_bounds__(128)
void scanB_k(const float* __restrict__ A_log)
{
    const int ch = blockIdx.x * 128 + threadIdx.x;
    const int d  = ch & (DINNER - 1);
    float Ar[16];
#pragma unroll
    for (int n = 0; n < 16; ++n) Ar[n] = -expf(A_log[d * DSTATE + n]);
    float h0[16];
#pragma unroll
    for (int n = 0; n < 16; ++n) h0[n] = 0.f;
    for (int c = 0; c < NCHK; ++c) {
#pragma unroll
        for (int n = 0; n < 16; ++n)
            g_h0[((size_t)c * DSTATE + n) * BL + ch] = h0[n];
        const float sd = g_sumdt[(size_t)c * BL + ch];
#pragma unroll
        for (int n = 0; n < 16; ++n)
            h0[n] = __expf(Ar[n] * sd) * h0[n] + g_hloc[((size_t)c * DSTATE + n) * BL + ch];
    }
}

__global__ __launch_bounds__(128)
void scanC_k(const float* __restrict__ delta, const float* __restrict__ xdbl,
             const float* __restrict__ u, const float* __restrict__ A_log,
             const float* __restrict__ Dv, const float* __restrict__ xz,
             __half* __restrict__ yh, __half* __restrict__ yl)
{
    __shared__ float sBC[4][32];
    const int tid = threadIdx.x;
    const int ch  = blockIdx.x * 128 + tid;
    const int b   = ch >> 11;
    const int d   = ch & (DINNER - 1);
    const int chunk = blockIdx.y;

    float Ar[16];
#pragma unroll
    for (int n = 0; n < 16; ++n) Ar[n] = -expf(A_log[d * DSTATE + n]);
    const float A0 = Ar[0];
    bool structured = true;
#pragma unroll
    for (int n = 1; n < 16; ++n)
        if (fabsf(Ar[n] - A0 * (float)(n + 1)) > 1e-4f * fabsf(Ar[n])) structured = false;

    const float Dd = Dv[d];
    float h[16];
#pragma unroll
    for (int n = 0; n < 16; ++n)
        h[n] = g_h0[((size_t)chunk * DSTATE + n) * BL + ch];

    const size_t rowbase = (size_t)b * LSEQ + chunk * TCH;
    const int sj = tid >> 5, sc = tid & 31;

    for (int tt = 0; tt < TCH; tt += 4) {
        sBC[sj][sc] = xdbl[(rowbase + tt + sj) * XDW + DTRANK + sc];
        float cd[4], cu[4], cr[4];
#pragma unroll
        for (int j = 0; j < 4; ++j) {
            const size_t ix = (rowbase + tt + j) * DINNER + d;
            cd[j] = delta[ix]; cu[j] = u[ix];
            cr[j] = xz[(rowbase + tt + j) * (2 * DINNER) + DINNER + d];
        }
        __syncthreads();
#pragma unroll
        for (int j = 0; j < 4; ++j) {
            const float dt = cd[j], ut = cu[j], du = dt * ut;
            float yv0 = 0.f, yv1 = 0.f, yv2 = 0.f, yv3 = 0.f;
            if (structured) {
                const float p = __expf(dt * A0);
                float wv[16];
                wv[0] = p;
#pragma unroll
                for (int n = 1; n < 16; ++n) wv[n] = wv[(n - 1) >> 1] * wv[n >> 1];
#pragma unroll
                for (int n = 0; n < 16; n += 4) {
                    h[n]     = wv[n]     * h[n]     + sBC[j][n]     * du;
                    h[n + 1] = wv[n + 1] * h[n + 1] + sBC[j][n + 1] * du;
                    h[n + 2] = wv[n + 2] * h[n + 2] + sBC[j][n + 2] * du;
                    h[n + 3] = wv[n + 3] * h[n + 3] + sBC[j][n + 3] * du;
                    yv0 += h[n]     * sBC[j][16 + n];
                    yv1 += h[n + 1] * sBC[j][16 + n + 1];
                    yv2 += h[n + 2] * sBC[j][16 + n + 2];
                    yv3 += h[n + 3] * sBC[j][16 + n + 3];
                }
            } else {
#pragma unroll
                for (int n = 0; n < 16; n += 4) {
                    const float w0 = __expf(dt * Ar[n]);
                    const float w1 = __expf(dt * Ar[n + 1]);
                    const float w2 = __expf(dt * Ar[n + 2]);
                    const float w3 = __expf(dt * Ar[n + 3]);
                    h[n]     = w0 * h[n]     + sBC[j][n]     * du;
                    h[n + 1] = w1 * h[n + 1] + sBC[j][n + 1] * du;
                    h[n + 2] = w2 * h[n + 2] + sBC[j][n + 2] * du;
                    h[n + 3] = w3 * h[n + 3] + sBC[j][n + 3] * du;
                    yv0 += h[n]     * sBC[j][16 + n];
                    yv1 += h[n + 1] * sBC[j][16 + n + 1];
                    yv2 += h[n + 2] * sBC[j][16 + n + 2];
                    yv3 += h[n + 3] * sBC[j][16 + n + 3];
                }
            }
            const float yv = (yv0 + yv1) + (yv2 + yv3);
            const float vout = (yv + ut * Dd) * silu_f(cr[j]);
            __half hh, ll; split_hl_h(vout, hh, ll);
            const size_t ix = (rowbase + tt + j) * DINNER + d;
            yh[ix] = hh; yl[ix] = ll;
        }
        __syncthreads();
    }
}

// ---------------- launch ----------------
extern "C" void kernel_launch(void* const* d_in, const int* in_sizes, int n_in,
                              void* d_out, int out_size)
{
    const float* x     = (const float*)d_in[0];
    const float* W_in  = (const float*)d_in[1];
    const float* convw = (const float*)d_in[2];
    const float* convb = (const float*)d_in[3];
    const float* W_x   = (const float*)d_in[4];
    const float* W_dt  = (const float*)d_in[5];
    const float* b_dt  = (const float*)d_in[6];
    const float* A_log = (const float*)d_in[7];
    const float* Dv    = (const float*)d_in[8];
    const float* W_out = (const float*)d_in[9];
    float* out = (float*)d_out;

    float *xz, *u, *xdbl, *delta, *part;
    __half *xh16, *xl16, *wih16, *woh16, *yh16, *yl16;
    __nv_bfloat16 *wdh, *wdl, *wxh, *wxl, *uh, *ul, *dth, *dtl;
    cudaGetSymbolAddress((void**)&xz,    g_xz);
    cudaGetSymbolAddress((void**)&u,     g_u);
    cudaGetSymbolAddress((void**)&xdbl,  g_xdbl);
    cudaGetSymbolAddress((void**)&delta, g_delta);
    cudaGetSymbolAddress((void**)&part,  g_part);
    cudaGetSymbolAddress((void**)&xh16,  g_xh16);  cudaGetSymbolAddress((void**)&xl16, g_xl16);
    cudaGetSymbolAddress((void**)&wih16, g_wih16);
    cudaGetSymbolAddress((void**)&woh16, g_woh16);
    cudaGetSymbolAddress((void**)&yh16,  g_yh16);  cudaGetSymbolAddress((void**)&yl16, g_yl16);
    cudaGetSymbolAddress((void**)&wdh, g_wdh); cudaGetSymbolAddress((void**)&wdl, g_wdl);
    cudaGetSymbolAddress((void**)&wxh, g_wxh); cudaGetSymbolAddress((void**)&wxl, g_wxl);
    cudaGetSymbolAddress((void**)&uh,  g_uh);  cudaGetSymbolAddress((void**)&ul,  g_ul);
    cudaGetSymbolAddress((void**)&dth, g_dth); cudaGetSymbolAddress((void**)&dtl, g_dtl);

    constexpr int SMEM128 = 2 * (2 * 128 * A_STRIDE + 2 * B_MAT_SZ) * 2;   // 75776 B
    constexpr int SMEM64  = 2 * (2 * 64  * A_STRIDE + 2 * B_MAT_SZ) * 2;   // 55296 B
    constexpr int SMEMF16 = 2 * (2 * 128 * AF_STRIDE + BF_MAT) * 2;        // 108544 B
    cudaFuncSetAttribute(gemm_bf16x3_k<128>, cudaFuncAttributeMaxDynamicSharedMemorySize, SMEM128);
    cudaFuncSetAttribute(gemm3_splitk_k,     cudaFuncAttributeMaxDynamicSharedMemorySize, SMEM64);
    cudaFuncSetAttribute(gemm_f16x2_k,       cudaFuncAttributeMaxDynamicSharedMemorySize, SMEMF16);

    // 1,2,3: conversions needed by GEMM1/GEMM3
    cvt_hilo_h_k<<<(BL * DMODEL / 4 + 255) / 256, 256>>>(x, xh16, xl16, BL * DMODEL / 4);
    cvt_h_k<<<(DMODEL * 2 * DINNER / 4 + 255) / 256, 256>>>(W_in, wih16, DMODEL * 2 * DINNER / 4);
    cvt_pad_wx_k<<<(DINNER * XDW) / 256, 256>>>(W_x, wxh, wxl);

    // 4: xz = x @ W_in   fp16 2-MMA BK=64  [4096,1024]@[1024,4096]
    gemm_f16x2_k<<<dim3((2 * DINNER) / 128, BL / 128), 256, SMEMF16>>>(
        xh16, xl16, wih16, xz, BL, 2 * DINNER, DMODEL, DMODEL);

    // 5: u = silu(causal_dwconv(xs) + b)  (+ bf16 hi/lo)
    conv_silu_kernel<<<(BL * DINNER / 4) / 256, 256>>>(xz, convw, convb, u, uh, ul);

    // 6: x_dbl = u @ W_x (padded N=128), split-K x4 -> partials (bf16 3-MMA)
    gemm3_splitk_k<<<dim3(KSPLIT, BL / 64), 256, SMEM64>>>(uh, ul, wxh, wxl, part);

    // 7: reduce partials -> xdbl fp32 + dt bf16 hi/lo
    reduce_xdbl_k<<<(BL * XDW) / 256, 256>>>(xdbl, dth, dtl);

    // 8: W_dt conversion (bf16)
    cvt_hilo_k<<<(DTRANK * DINNER / 4 + 255) / 256, 256>>>(W_dt, wdh, wdl, DTRANK * DINNER / 4);

    // 9: delta = softplus(dt @ W_dt + b_dt)  bf16 3-MMA  [4096,64(str128)]@[64,2048]
    gemm_bf16x3_k<128><<<dim3(DINNER / 128, BL / 128), 256, SMEM128>>>(
        dth, dtl, wdh, wdl, delta, BL, DINNER, DTRANK, XDW, b_dt, 1, nullptr, nullptr);

    // 10-12: chunked selective scan (emits y as fp16 hi/lo)
    scanA_k<<<dim3(BL / 128, NCHK), 128>>>(delta, xdbl, u, A_log);
    scanB_k<<<BL / 128, 128>>>(A_log);
    scanC_k<<<dim3(BL / 128, NCHK), 128>>>(delta, xdbl, u, A_log, Dv, xz, yh16, yl16);

    // 13: W_out conversion (fp16)
    cvt_h_k<<<(DINNER * DMODEL / 4 + 255) / 256, 256>>>(W_out, woh16, DINNER * DMODEL / 4);

    // 14: out = y @ W_out   fp16 2-MMA BK=64  [4096,2048]@[2048,1024]
    gemm_f16x2_k<<<dim3(DMODEL / 128, BL / 128), 256, SMEMF16>>>(
        yh16, yl16, woh16, out, BL, DMODEL, DINNER, DINNER);
}